// round 7
// baseline (speedup 1.0000x reference)
#include <cuda_runtime.h>
#include <cstdint>
#include <cstddef>

#define S_LEN 2048
#define HID   4096
#define NH    32
#define HD    128
#define P3    12288   // 3*HID
#define NORM  0.08838834764831845f   // 1/sqrt(128)

// ---------------- scratch (no allocations allowed) ----------------
__device__ float g_proj[S_LEN * P3];   // QKV after projection (RoPE applied in-place)
__device__ float g_attn[S_LEN * HID];  // attention output, [s, h*128+d] layout

__device__ __forceinline__ uint32_t f2tf32(float x) {
    uint32_t r;
    asm("cvt.rna.tf32.f32 %0, %1;" : "=r"(r) : "f"(x));
    return r;
}

// mma.sync m16n8k8 tf32 (base ISA)
__device__ __forceinline__ void mma_tf32(float& c0, float& c1, float& c2, float& c3,
                                         uint32_t a0, uint32_t a1, uint32_t a2, uint32_t a3,
                                         uint32_t b0, uint32_t b1) {
    asm volatile(
        "mma.sync.aligned.m16n8k8.row.col.f32.tf32.tf32.f32 "
        "{%0,%1,%2,%3}, {%4,%5,%6,%7}, {%8,%9}, {%0,%1,%2,%3};"
        : "+f"(c0), "+f"(c1), "+f"(c2), "+f"(c3)
        : "r"(a0), "r"(a1), "r"(a2), "r"(a3), "r"(b0), "r"(b1));
}

// mma.sync m16n8k16 bf16 (base ISA)
__device__ __forceinline__ void mma_bf16(float& c0, float& c1, float& c2, float& c3,
                                         uint32_t a0, uint32_t a1, uint32_t a2, uint32_t a3,
                                         uint32_t b0, uint32_t b1) {
    asm volatile(
        "mma.sync.aligned.m16n8k16.row.col.f32.bf16.bf16.f32 "
        "{%0,%1,%2,%3}, {%4,%5,%6,%7}, {%8,%9}, {%0,%1,%2,%3};"
        : "+f"(c0), "+f"(c1), "+f"(c2), "+f"(c3)
        : "r"(a0), "r"(a1), "r"(a2), "r"(a3), "r"(b0), "r"(b1));
}

// split x into hi(bf16) + lo(bf16); pack two adjacent k-elements per b32
__device__ __forceinline__ void split_pair(float x0, float x1, uint32_t& hp, uint32_t& lp) {
    uint16_t h0, h1, l0, l1;
    asm("cvt.rn.bf16.f32 %0, %1;" : "=h"(h0) : "f"(x0));
    asm("cvt.rn.bf16.f32 %0, %1;" : "=h"(h1) : "f"(x1));
    float r0 = x0 - __uint_as_float((uint32_t)h0 << 16);
    float r1 = x1 - __uint_as_float((uint32_t)h1 << 16);
    asm("cvt.rn.bf16.f32 %0, %1;" : "=h"(l0) : "f"(r0));
    asm("cvt.rn.bf16.f32 %0, %1;" : "=h"(l1) : "f"(r1));
    asm("mov.b32 %0, {%1, %2};" : "=r"(hp) : "h"(h0), "h"(h1));
    asm("mov.b32 %0, {%1, %2};" : "=r"(lp) : "h"(l0), "h"(l1));
}

// ---------------- tf32 mma GEMM v2: C[M,N] = A[M,K] * B[N,K]^T ----------------
// Block 128x128x32, 512 threads (16 warps, 4/SMSP), warp tile 32x32, double-buffered.
// SMEM: [row][36] fp32 (pad -> frag LDS bank = (4g+cc)%32, conflict-free).
#define GBK    32
#define SROW_G 36
#define GEMM_SMEM (4 * 128 * SROW_G * 4)   // A[2] + B[2] stages = 73728 B

__global__ __launch_bounds__(512, 1) void gemm_tf32mma(const float* __restrict__ A,
                                                       const float* __restrict__ B,
                                                       float* __restrict__ C,
                                                       int M, int N, int K) {
    extern __shared__ float smem[];
    float* As = smem;                       // [2][128][36]
    float* Bs = smem + 2 * 128 * SROW_G;    // [2][128][36]

    const int t = threadIdx.x;
    const int w = t >> 5, lane = t & 31;
    const int wm = w >> 2, wn = w & 3;      // warp grid 4x4 -> 32x32 per warp
    const int g = lane >> 2, cc = lane & 3;
    const int m0 = blockIdx.y * 128, n0 = blockIdx.x * 128;
    const int KT = K / GBK;

    // global loads: 128 rows x 32 cols per tile; thread row t>>3 (+64), float4 col t&7
    const int lrow = t >> 3, lc4 = (t & 7) * 4;
    const float* Ab = A + (size_t)(m0 + lrow) * K + lc4;
    const float* Bb = B + (size_t)(n0 + lrow) * K + lc4;
    const size_t rstep = (size_t)64 * K;

    float4 ra[2], rb[2];
#pragma unroll
    for (int i = 0; i < 2; i++) { ra[i] = *(const float4*)(Ab + i * rstep); }
#pragma unroll
    for (int i = 0; i < 2; i++) { rb[i] = *(const float4*)(Bb + i * rstep); }
#pragma unroll
    for (int i = 0; i < 2; i++) {
        uint4 va = {f2tf32(ra[i].x), f2tf32(ra[i].y), f2tf32(ra[i].z), f2tf32(ra[i].w)};
        *(uint4*)&As[(lrow + 64 * i) * SROW_G + lc4] = va;
        uint4 vb = {f2tf32(rb[i].x), f2tf32(rb[i].y), f2tf32(rb[i].z), f2tf32(rb[i].w)};
        *(uint4*)&Bs[(lrow + 64 * i) * SROW_G + lc4] = vb;
    }
    __syncthreads();

    float acc[2][4][4];   // [mt][nt][frag]
#pragma unroll
    for (int mt = 0; mt < 2; mt++)
#pragma unroll
        for (int nt = 0; nt < 4; nt++)
#pragma unroll
            for (int q = 0; q < 4; q++) acc[mt][nt][q] = 0.f;

    for (int kt = 0; kt < KT; kt++) {
        const int cur = kt & 1;
        const bool hasnext = (kt + 1 < KT);
        if (hasnext) {
            const float* Ap = Ab + (size_t)(kt + 1) * GBK;
            const float* Bp = Bb + (size_t)(kt + 1) * GBK;
#pragma unroll
            for (int i = 0; i < 2; i++) ra[i] = *(const float4*)(Ap + i * rstep);
#pragma unroll
            for (int i = 0; i < 2; i++) rb[i] = *(const float4*)(Bp + i * rstep);
        }
        const float* Ac = As + cur * 128 * SROW_G;
        const float* Bc = Bs + cur * 128 * SROW_G;
#pragma unroll
        for (int kc = 0; kc < GBK; kc += 8) {
            uint32_t af[2][4];
#pragma unroll
            for (int mt = 0; mt < 2; mt++) {
                const int r = wm * 32 + mt * 16 + g;
                af[mt][0] = __float_as_uint(Ac[r * SROW_G + kc + cc]);
                af[mt][1] = __float_as_uint(Ac[(r + 8) * SROW_G + kc + cc]);
                af[mt][2] = __float_as_uint(Ac[r * SROW_G + kc + cc + 4]);
                af[mt][3] = __float_as_uint(Ac[(r + 8) * SROW_G + kc + cc + 4]);
            }
            uint32_t bf[4][2];
#pragma unroll
            for (int nt = 0; nt < 4; nt++) {
                const int n = wn * 32 + nt * 8 + g;
                bf[nt][0] = __float_as_uint(Bc[n * SROW_G + kc + cc]);
                bf[nt][1] = __float_as_uint(Bc[n * SROW_G + kc + cc + 4]);
            }
#pragma unroll
            for (int mt = 0; mt < 2; mt++)
#pragma unroll
                for (int nt = 0; nt < 4; nt++)
                    mma_tf32(acc[mt][nt][0], acc[mt][nt][1], acc[mt][nt][2], acc[mt][nt][3],
                             af[mt][0], af[mt][1], af[mt][2], af[mt][3],
                             bf[nt][0], bf[nt][1]);
        }
        __syncthreads();
        if (hasnext) {
            const int nxt = cur ^ 1;
            float* An = As + nxt * 128 * SROW_G;
            float* Bn = Bs + nxt * 128 * SROW_G;
#pragma unroll
            for (int i = 0; i < 2; i++) {
                uint4 va = {f2tf32(ra[i].x), f2tf32(ra[i].y), f2tf32(ra[i].z), f2tf32(ra[i].w)};
                *(uint4*)&An[(lrow + 64 * i) * SROW_G + lc4] = va;
                uint4 vb = {f2tf32(rb[i].x), f2tf32(rb[i].y), f2tf32(rb[i].z), f2tf32(rb[i].w)};
                *(uint4*)&Bn[(lrow + 64 * i) * SROW_G + lc4] = vb;
            }
            __syncthreads();
        }
    }

#pragma unroll
    for (int mt = 0; mt < 2; mt++) {
        const int r = m0 + wm * 32 + mt * 16 + g;
#pragma unroll
        for (int nt = 0; nt < 4; nt++) {
            const int n = n0 + wn * 32 + nt * 8 + 2 * cc;
            *(float2*)&C[(size_t)r * N + n]       = make_float2(acc[mt][nt][0], acc[mt][nt][1]);
            *(float2*)&C[(size_t)(r + 8) * N + n] = make_float2(acc[mt][nt][2], acc[mt][nt][3]);
        }
    }
}

// ---------------- RoPE v2: one block per sequence position, smem trig table ----------------
__global__ __launch_bounds__(256) void rope2_kernel(float* __restrict__ proj,
                                                    const int* __restrict__ pos_ids) {
    __shared__ float ca[64], sa[64];
    const int s = blockIdx.x;
    const int t = threadIdx.x;
    if (t < 64) {
        const int pos = pos_ids[s];
        double inv = exp(-((double)t / 64.0) * 9.210340371976184);  // ln(10000)
        double a = (double)pos * inv;
        const double twopi = 6.283185307179586476925286766559;
        a -= floor(a / twopi) * twopi;
        sa[t] = sinf((float)a);
        ca[t] = cosf((float)a);
    }
    __syncthreads();
    float* base = proj + (size_t)s * P3;
#pragma unroll
    for (int it = 0; it < 16; it++) {
        const int p = t + it * 256;
        const int d = p & 63;
        const int hh = (p >> 6) & 31;
        float* ptr = base + ((p >> 11) ? HID : 0) + hh * HD + d;
        const float x1 = ptr[0], x2 = ptr[64];
        const float c = ca[d], sn = sa[d];
        ptr[0]  = x1 * c - x2 * sn;
        ptr[64] = x2 * c + x1 * sn;
    }
}

// ---------------- bf16-split tensor-core flash attention (unchanged from R5) ----------------
#define QSTR 136
#define VSTR 72
#define SSTR 65
#define OFF_QH  0
#define OFF_QL  (OFF_QH + 128 * QSTR * 2)
#define OFF_KH  (OFF_QL + 128 * QSTR * 2)
#define OFF_KL  (OFF_KH + 64 * QSTR * 2)
#define OFF_VTH (OFF_KL + 64 * QSTR * 2)
#define OFF_VTL (OFF_VTH + 128 * VSTR * 2)
#define OFF_SF  (OFF_VTL + 128 * VSTR * 2)
#define OFF_PH  (OFF_SF + 128 * SSTR * 4)
#define OFF_PL  (OFF_PH + 128 * VSTR * 2)
#define OFF_ST  (OFF_PL + 128 * VSTR * 2)
#define ATTN2_SMEM (OFF_ST + 3 * 128 * 4)

__global__ __launch_bounds__(256, 1) void attn_bf16(const float* __restrict__ proj,
                                                    float* __restrict__ attn_out) {
    extern __shared__ char smraw[];
    uint32_t* Qh  = (uint32_t*)(smraw + OFF_QH);
    uint32_t* Ql  = (uint32_t*)(smraw + OFF_QL);
    uint32_t* Kh  = (uint32_t*)(smraw + OFF_KH);
    uint32_t* Kl  = (uint32_t*)(smraw + OFF_KL);
    uint32_t* Vth = (uint32_t*)(smraw + OFF_VTH);
    uint32_t* Vtl = (uint32_t*)(smraw + OFF_VTL);
    float*    Sf  = (float*)(smraw + OFF_SF);
    uint32_t* Ph  = (uint32_t*)(smraw + OFF_PH);
    uint32_t* Pl  = (uint32_t*)(smraw + OFF_PL);
    float*    rowM = (float*)(smraw + OFF_ST);
    float*    rowL = rowM + 128;
    float*    rowA = rowL + 128;

    const int t = threadIdx.x;
    const int w = t >> 5, lane = t & 31;
    const int g = lane >> 2, cc = lane & 3;
    const int h = blockIdx.x;
    const int qt = 15 - (int)blockIdx.y;
    const int qbase = qt * 128;
    const int qcol = h * HD, kcol = HID + h * HD, vcol = 2 * HID + h * HD;

    {
        const int row = t >> 1;
        const int c0 = (t & 1) * 64;
        const float* src = proj + (size_t)(qbase + row) * P3 + qcol + c0;
        uint32_t* qh = Qh + row * 68 + (c0 >> 1);
        uint32_t* ql = Ql + row * 68 + (c0 >> 1);
#pragma unroll
        for (int i = 0; i < 16; i++) {
            float4 v = *(const float4*)(src + i * 4);
            uint32_t hp, lp;
            split_pair(v.x * NORM, v.y * NORM, hp, lp);
            qh[2 * i] = hp; ql[2 * i] = lp;
            split_pair(v.z * NORM, v.w * NORM, hp, lp);
            qh[2 * i + 1] = hp; ql[2 * i + 1] = lp;
        }
    }
    if (t < 128) { rowM[t] = -3.0e38f; rowL[t] = 0.f; }

    float oacc[16][4];
#pragma unroll
    for (int nt = 0; nt < 16; nt++)
#pragma unroll
        for (int q = 0; q < 4; q++) oacc[nt][q] = 0.f;

    const int nkt = 2 * qt + 2;
    for (int j = 0; j < nkt; j++) {
        __syncthreads();
        {
            const int r = t >> 2;
            const int c0 = (t & 3) * 32;
            const float* src = proj + (size_t)(j * 64 + r) * P3 + kcol + c0;
            uint32_t* kh = Kh + r * 68 + (c0 >> 1);
            uint32_t* kl = Kl + r * 68 + (c0 >> 1);
#pragma unroll
            for (int i = 0; i < 8; i++) {
                float4 v = *(const float4*)(src + i * 4);
                uint32_t hp, lp;
                split_pair(v.x, v.y, hp, lp);
                kh[2 * i] = hp; kl[2 * i] = lp;
                split_pair(v.z, v.w, hp, lp);
                kh[2 * i + 1] = hp; kl[2 * i + 1] = lp;
            }
        }
        {
            const int c = (t & 31) + ((t >> 5) & 3) * 32;
            const int rp0 = (t >> 7) * 16;
            const float* vsrc = proj + (size_t)(j * 64) * P3 + vcol + c;
#pragma unroll
            for (int it = 0; it < 16; it++) {
                const int rp = rp0 + it;
                const float v0 = vsrc[(size_t)(2 * rp) * P3];
                const float v1 = vsrc[(size_t)(2 * rp + 1) * P3];
                uint32_t hp, lp;
                split_pair(v0, v1, hp, lp);
                Vth[c * 36 + rp] = hp;
                Vtl[c * 36 + rp] = lp;
            }
        }
        __syncthreads();

        float sacc[8][4];
#pragma unroll
        for (int nt = 0; nt < 8; nt++)
#pragma unroll
            for (int q = 0; q < 4; q++) sacc[nt][q] = 0.f;

        const uint32_t* q0 = Qh + (w * 16 + g) * 68;
        const uint32_t* q1 = q0 + 8 * 68;
        const uint32_t* q0l = Ql + (w * 16 + g) * 68;
        const uint32_t* q1l = q0l + 8 * 68;
#pragma unroll
        for (int kc = 0; kc < 8; kc++) {
            const int kw = kc * 8;
            uint32_t ah0 = q0[kw + cc], ah1 = q1[kw + cc];
            uint32_t ah2 = q0[kw + cc + 4], ah3 = q1[kw + cc + 4];
            uint32_t al0 = q0l[kw + cc], al1 = q1l[kw + cc];
            uint32_t al2 = q0l[kw + cc + 4], al3 = q1l[kw + cc + 4];
#pragma unroll
            for (int nt = 0; nt < 8; nt++) {
                const int nw = (nt * 8 + g) * 68 + kw;
                uint32_t bh0 = Kh[nw + cc], bh1 = Kh[nw + cc + 4];
                uint32_t bl0 = Kl[nw + cc], bl1 = Kl[nw + cc + 4];
                mma_bf16(sacc[nt][0], sacc[nt][1], sacc[nt][2], sacc[nt][3],
                         ah0, ah1, ah2, ah3, bh0, bh1);
                mma_bf16(sacc[nt][0], sacc[nt][1], sacc[nt][2], sacc[nt][3],
                         ah0, ah1, ah2, ah3, bl0, bl1);
                mma_bf16(sacc[nt][0], sacc[nt][1], sacc[nt][2], sacc[nt][3],
                         al0, al1, al2, al3, bh0, bh1);
            }
        }
        {
            const bool diagt = (j * 64 + 63 > qbase);
            const int r0g = qbase + w * 16 + g;
            float* s0 = Sf + (w * 16 + g) * SSTR;
            float* s1 = s0 + 8 * SSTR;
#pragma unroll
            for (int nt = 0; nt < 8; nt++) {
                const int cg = j * 64 + nt * 8 + 2 * cc;
                float v0 = sacc[nt][0], v1 = sacc[nt][1];
                float v2 = sacc[nt][2], v3 = sacc[nt][3];
                if (diagt) {
                    if (cg     > r0g)     v0 = -1.0e9f;
                    if (cg + 1 > r0g)     v1 = -1.0e9f;
                    if (cg     > r0g + 8) v2 = -1.0e9f;
                    if (cg + 1 > r0g + 8) v3 = -1.0e9f;
                }
                s0[nt * 8 + 2 * cc] = v0; s0[nt * 8 + 2 * cc + 1] = v1;
                s1[nt * 8 + 2 * cc] = v2; s1[nt * 8 + 2 * cc + 1] = v3;
            }
        }
        __syncthreads();

        {
            const int row = t >> 1, half = t & 1;
            const float* pr = Sf + row * SSTR + half * 32;
            float m = -3.0e38f;
#pragma unroll 8
            for (int i = 0; i < 32; i++) m = fmaxf(m, pr[i]);
            m = fmaxf(m, __shfl_xor_sync(0xFFFFFFFFu, m, 1));
            const float mold = rowM[row];
            const float mnew = fmaxf(mold, m);
            float ssum = 0.f;
            uint32_t* ph = Ph + row * 36 + half * 16;
            uint32_t* pl = Pl + row * 36 + half * 16;
#pragma unroll 4
            for (int i = 0; i < 16; i++) {
                const float p0 = __expf(pr[2 * i] - mnew);
                const float p1 = __expf(pr[2 * i + 1] - mnew);
                ssum += p0 + p1;
                uint32_t hp, lp;
                split_pair(p0, p1, hp, lp);
                ph[i] = hp; pl[i] = lp;
            }
            ssum += __shfl_xor_sync(0xFFFFFFFFu, ssum, 1);
            if (half == 0) {
                const float alpha = __expf(mold - mnew);
                rowA[row] = alpha;
                rowL[row] = rowL[row] * alpha + ssum;
                rowM[row] = mnew;
            }
        }
        __syncthreads();

        {
            const float al0 = rowA[w * 16 + g], al1 = rowA[w * 16 + 8 + g];
#pragma unroll
            for (int nt = 0; nt < 16; nt++) {
                oacc[nt][0] *= al0; oacc[nt][1] *= al0;
                oacc[nt][2] *= al1; oacc[nt][3] *= al1;
            }
            const uint32_t* p0 = Ph + (w * 16 + g) * 36;
            const uint32_t* p1 = p0 + 8 * 36;
            const uint32_t* p0l = Pl + (w * 16 + g) * 36;
            const uint32_t* p1l = p0l + 8 * 36;
#pragma unroll
            for (int kc = 0; kc < 4; kc++) {
                const int kw = kc * 8;
                uint32_t ah0 = p0[kw + cc], ah1 = p1[kw + cc];
                uint32_t ah2 = p0[kw + cc + 4], ah3 = p1[kw + cc + 4];
                uint32_t al0f = p0l[kw + cc], al1f = p1l[kw + cc];
                uint32_t al2f = p0l[kw + cc + 4], al3f = p1l[kw + cc + 4];
#pragma unroll
                for (int nt = 0; nt < 16; nt++) {
                    const int nw = (nt * 8 + g) * 36 + kw;
                    uint32_t bh0 = Vth[nw + cc], bh1 = Vth[nw + cc + 4];
                    uint32_t bl0 = Vtl[nw + cc], bl1 = Vtl[nw + cc + 4];
                    mma_bf16(oacc[nt][0], oacc[nt][1], oacc[nt][2], oacc[nt][3],
                             ah0, ah1, ah2, ah3, bh0, bh1);
                    mma_bf16(oacc[nt][0], oacc[nt][1], oacc[nt][2], oacc[nt][3],
                             ah0, ah1, ah2, ah3, bl0, bl1);
                    mma_bf16(oacc[nt][0], oacc[nt][1], oacc[nt][2], oacc[nt][3],
                             al0f, al1f, al2f, al3f, bh0, bh1);
                }
            }
        }
    }

    {
        const float il0 = 1.0f / rowL[w * 16 + g];
        const float il1 = 1.0f / rowL[w * 16 + 8 + g];
        const size_t base0 = (size_t)(qbase + w * 16 + g) * HID + h * HD + 2 * cc;
#pragma unroll
        for (int nt = 0; nt < 16; nt++) {
            *(float2*)(attn_out + base0 + nt * 8) =
                make_float2(oacc[nt][0] * il0, oacc[nt][1] * il0);
            *(float2*)(attn_out + base0 + 8 * HID + nt * 8) =
                make_float2(oacc[nt][2] * il1, oacc[nt][3] * il1);
        }
    }
}

// ---------------- launch ----------------
extern "C" void kernel_launch(void* const* d_in, const int* in_sizes, int n_in,
                              void* d_out, int out_size) {
    (void)in_sizes; (void)n_in; (void)out_size;
    const float* hidden  = (const float*)d_in[0];
    // d_in[1] = attention_mask: deterministic causal -> applied analytically
    const int*   pos_ids = (const int*)d_in[2];
    const float* W_pack  = (const float*)d_in[3];
    const float* W_o     = (const float*)d_in[4];
    float* out = (float*)d_out;

    float *proj = nullptr, *attn = nullptr;
    cudaGetSymbolAddress((void**)&proj, g_proj);
    cudaGetSymbolAddress((void**)&attn, g_attn);
    cudaFuncSetAttribute(gemm_tf32mma, cudaFuncAttributeMaxDynamicSharedMemorySize, GEMM_SMEM);
    cudaFuncSetAttribute(attn_bf16, cudaFuncAttributeMaxDynamicSharedMemorySize, ATTN2_SMEM);

    // 1) QKV projection: [2048,4096] @ [12288,4096]^T  (tf32 mma, 16 warps)
    gemm_tf32mma<<<dim3(P3 / 128, S_LEN / 128), 512, GEMM_SMEM>>>(hidden, W_pack, proj,
                                                                  S_LEN, P3, HID);
    // 2) RoPE in-place on Q,K
    rope2_kernel<<<S_LEN, 256>>>(proj, pos_ids);
    // 3) causal flash attention (bf16-split tensor cores, fp32-accurate)
    attn_bf16<<<dim3(NH, S_LEN / 128), 256, ATTN2_SMEM>>>(proj, attn);
    // 4) output projection: [2048,4096] @ [4096,4096]^T  (tf32 mma, 16 warps)
    gemm_tf32mma<<<dim3(HID / 128, S_LEN / 128), 512, GEMM_SMEM>>>(attn, W_o, out,
                                                                   S_LEN, HID, HID);
}

// round 8
// speedup vs baseline: 1.0377x; 1.0377x over previous
#include <cuda_runtime.h>
#include <cuda_fp16.h>
#include <cstdint>
#include <cstddef>

#define S_LEN 2048
#define HID   4096
#define NH    32
#define HD    128
#define P3    12288   // 3*HID
#define NORM  0.08838834764831845f   // 1/sqrt(128)

// ---------------- scratch (no allocations allowed) ----------------
__device__ float g_proj[S_LEN * P3];   // QKV after projection (RoPE applied in-place)
__device__ float g_attn[S_LEN * HID];  // attention output, [s, h*128+d] layout

// mma.sync m16n8k16 fp16, fp32 accum (base ISA)
__device__ __forceinline__ void mma_fp16(float& c0, float& c1, float& c2, float& c3,
                                         uint32_t a0, uint32_t a1, uint32_t a2, uint32_t a3,
                                         uint32_t b0, uint32_t b1) {
    asm volatile(
        "mma.sync.aligned.m16n8k16.row.col.f32.f16.f16.f32 "
        "{%0,%1,%2,%3}, {%4,%5,%6,%7}, {%8,%9}, {%0,%1,%2,%3};"
        : "+f"(c0), "+f"(c1), "+f"(c2), "+f"(c3)
        : "r"(a0), "r"(a1), "r"(a2), "r"(a3), "r"(b0), "r"(b1));
}

// mma.sync m16n8k16 bf16 (attention)
__device__ __forceinline__ void mma_bf16(float& c0, float& c1, float& c2, float& c3,
                                         uint32_t a0, uint32_t a1, uint32_t a2, uint32_t a3,
                                         uint32_t b0, uint32_t b1) {
    asm volatile(
        "mma.sync.aligned.m16n8k16.row.col.f32.bf16.bf16.f32 "
        "{%0,%1,%2,%3}, {%4,%5,%6,%7}, {%8,%9}, {%0,%1,%2,%3};"
        : "+f"(c0), "+f"(c1), "+f"(c2), "+f"(c3)
        : "r"(a0), "r"(a1), "r"(a2), "r"(a3), "r"(b0), "r"(b1));
}

__device__ __forceinline__ uint32_t pack_h2(float x0, float x1) {
    __half2 h = __floats2half2_rn(x0, x1);   // .x = x0 (low half)
    return *(uint32_t*)&h;
}

// split x into hi(bf16) + lo(bf16); pack two adjacent k-elements per b32
__device__ __forceinline__ void split_pair(float x0, float x1, uint32_t& hp, uint32_t& lp) {
    uint16_t h0, h1, l0, l1;
    asm("cvt.rn.bf16.f32 %0, %1;" : "=h"(h0) : "f"(x0));
    asm("cvt.rn.bf16.f32 %0, %1;" : "=h"(h1) : "f"(x1));
    float r0 = x0 - __uint_as_float((uint32_t)h0 << 16);
    float r1 = x1 - __uint_as_float((uint32_t)h1 << 16);
    asm("cvt.rn.bf16.f32 %0, %1;" : "=h"(l0) : "f"(r0));
    asm("cvt.rn.bf16.f32 %0, %1;" : "=h"(l1) : "f"(r1));
    asm("mov.b32 %0, {%1, %2};" : "=r"(hp) : "h"(h0), "h"(h1));
    asm("mov.b32 %0, {%1, %2};" : "=r"(lp) : "h"(l0), "h"(l1));
}

// ---------------- fp16 mma GEMM: C[M,N] = A[M,K] * B[N,K]^T ----------------
// Block 128x128x32 (2x k16 chunks), 256 threads (8 warps, 2x4), warp tile 64x32.
// fp16 inputs (11-bit mantissa == tf32), fp32 accum. Smem rows: 16 b32 words + 4 pad
// (stride 20) -> fragment LDS bank = (20g + cc + const)%32, all 32 lanes distinct.
#define KW   20                              // b32 words per smem row
__global__ __launch_bounds__(256, 2) void gemm_fp16mma(const float* __restrict__ A,
                                                       const float* __restrict__ B,
                                                       float* __restrict__ C,
                                                       int M, int N, int K) {
    __shared__ uint32_t Ah[2][128 * KW];     // 10 KB per stage
    __shared__ uint32_t Bh[2][128 * KW];

    const int t = threadIdx.x;
    const int w = t >> 5, lane = t & 31;
    const int wm = w >> 2, wn = w & 3;       // 2x4 warp grid, warp tile 64x32
    const int g = lane >> 2, cc = lane & 3;
    const int m0 = blockIdx.y * 128, n0 = blockIdx.x * 128;
    const int KT = K >> 5;

    // global loads: row t>>1, half (t&1): 16 cols = 4 float4 -> 8 fp16x2 words
    const int lrow = t >> 1, lhalf = t & 1;
    const float* Abase = A + (size_t)(m0 + lrow) * K + lhalf * 16;
    const float* Bbase = B + (size_t)(n0 + lrow) * K + lhalf * 16;
    const int wbase = lrow * KW + lhalf * 8;

    uint32_t au[8], bu[8];
#pragma unroll
    for (int i = 0; i < 4; i++) {
        float4 va = *(const float4*)(Abase + 4 * i);
        au[2 * i] = pack_h2(va.x, va.y); au[2 * i + 1] = pack_h2(va.z, va.w);
        float4 vb = *(const float4*)(Bbase + 4 * i);
        bu[2 * i] = pack_h2(vb.x, vb.y); bu[2 * i + 1] = pack_h2(vb.z, vb.w);
    }
#pragma unroll
    for (int i = 0; i < 4; i++) {
        *(uint2*)&Ah[0][wbase + 2 * i] = make_uint2(au[2 * i], au[2 * i + 1]);
        *(uint2*)&Bh[0][wbase + 2 * i] = make_uint2(bu[2 * i], bu[2 * i + 1]);
    }
    __syncthreads();

    float acc[4][4][4];   // [mt][nt][frag]
#pragma unroll
    for (int mt = 0; mt < 4; mt++)
#pragma unroll
        for (int nt = 0; nt < 4; nt++)
#pragma unroll
            for (int q = 0; q < 4; q++) acc[mt][nt][q] = 0.f;

    for (int kt = 0; kt < KT; kt++) {
        const int cur = kt & 1;
        const bool hasnext = (kt + 1 < KT);
        if (hasnext) {
            const float* Ap = Abase + (size_t)(kt + 1) * 32;
            const float* Bp = Bbase + (size_t)(kt + 1) * 32;
#pragma unroll
            for (int i = 0; i < 4; i++) {
                float4 va = *(const float4*)(Ap + 4 * i);
                au[2 * i] = pack_h2(va.x, va.y); au[2 * i + 1] = pack_h2(va.z, va.w);
                float4 vb = *(const float4*)(Bp + 4 * i);
                bu[2 * i] = pack_h2(vb.x, vb.y); bu[2 * i + 1] = pack_h2(vb.z, vb.w);
            }
        }
        const uint32_t* Ac = Ah[cur];
        const uint32_t* Bc = Bh[cur];
#pragma unroll
        for (int h = 0; h < 2; h++) {            // two k16 chunks
            const int kw = h * 8;
            uint32_t af[4][4];
#pragma unroll
            for (int mt = 0; mt < 4; mt++) {
                const int r = (wm * 64 + mt * 16 + g) * KW + kw;
                af[mt][0] = Ac[r + cc];
                af[mt][1] = Ac[r + 8 * KW + cc];
                af[mt][2] = Ac[r + cc + 4];
                af[mt][3] = Ac[r + 8 * KW + cc + 4];
            }
            uint32_t bf[4][2];
#pragma unroll
            for (int nt = 0; nt < 4; nt++) {
                const int n = (wn * 32 + nt * 8 + g) * KW + kw;
                bf[nt][0] = Bc[n + cc];
                bf[nt][1] = Bc[n + cc + 4];
            }
#pragma unroll
            for (int mt = 0; mt < 4; mt++)
#pragma unroll
                for (int nt = 0; nt < 4; nt++)
                    mma_fp16(acc[mt][nt][0], acc[mt][nt][1], acc[mt][nt][2], acc[mt][nt][3],
                             af[mt][0], af[mt][1], af[mt][2], af[mt][3],
                             bf[nt][0], bf[nt][1]);
        }
        __syncthreads();
        if (hasnext) {
            const int nxt = cur ^ 1;
#pragma unroll
            for (int i = 0; i < 4; i++) {
                *(uint2*)&Ah[nxt][wbase + 2 * i] = make_uint2(au[2 * i], au[2 * i + 1]);
                *(uint2*)&Bh[nxt][wbase + 2 * i] = make_uint2(bu[2 * i], bu[2 * i + 1]);
            }
            __syncthreads();
        }
    }

#pragma unroll
    for (int mt = 0; mt < 4; mt++) {
        const int r = m0 + wm * 64 + mt * 16 + g;
#pragma unroll
        for (int nt = 0; nt < 4; nt++) {
            const int n = n0 + wn * 32 + nt * 8 + 2 * cc;
            *(float2*)&C[(size_t)r * N + n]       = make_float2(acc[mt][nt][0], acc[mt][nt][1]);
            *(float2*)&C[(size_t)(r + 8) * N + n] = make_float2(acc[mt][nt][2], acc[mt][nt][3]);
        }
    }
}

// ---------------- RoPE v2: one block per sequence position, smem trig table ----------------
__global__ __launch_bounds__(256) void rope2_kernel(float* __restrict__ proj,
                                                    const int* __restrict__ pos_ids) {
    __shared__ float ca[64], sa[64];
    const int s = blockIdx.x;
    const int t = threadIdx.x;
    if (t < 64) {
        const int pos = pos_ids[s];
        double inv = exp(-((double)t / 64.0) * 9.210340371976184);  // ln(10000)
        double a = (double)pos * inv;
        const double twopi = 6.283185307179586476925286766559;
        a -= floor(a / twopi) * twopi;
        sa[t] = sinf((float)a);
        ca[t] = cosf((float)a);
    }
    __syncthreads();
    float* base = proj + (size_t)s * P3;
#pragma unroll
    for (int it = 0; it < 16; it++) {
        const int p = t + it * 256;
        const int d = p & 63;
        const int hh = (p >> 6) & 31;
        float* ptr = base + ((p >> 11) ? HID : 0) + hh * HD + d;
        const float x1 = ptr[0], x2 = ptr[64];
        const float c = ca[d], sn = sa[d];
        ptr[0]  = x1 * c - x2 * sn;
        ptr[64] = x2 * c + x1 * sn;
    }
}

// ---------------- bf16-split tensor-core flash attention (unchanged) ----------------
#define QSTR 136
#define VSTR 72
#define SSTR 65
#define OFF_QH  0
#define OFF_QL  (OFF_QH + 128 * QSTR * 2)
#define OFF_KH  (OFF_QL + 128 * QSTR * 2)
#define OFF_KL  (OFF_KH + 64 * QSTR * 2)
#define OFF_VTH (OFF_KL + 64 * QSTR * 2)
#define OFF_VTL (OFF_VTH + 128 * VSTR * 2)
#define OFF_SF  (OFF_VTL + 128 * VSTR * 2)
#define OFF_PH  (OFF_SF + 128 * SSTR * 4)
#define OFF_PL  (OFF_PH + 128 * VSTR * 2)
#define OFF_ST  (OFF_PL + 128 * VSTR * 2)
#define ATTN2_SMEM (OFF_ST + 3 * 128 * 4)

__global__ __launch_bounds__(256, 1) void attn_bf16(const float* __restrict__ proj,
                                                    float* __restrict__ attn_out) {
    extern __shared__ char smraw[];
    uint32_t* Qh  = (uint32_t*)(smraw + OFF_QH);
    uint32_t* Ql  = (uint32_t*)(smraw + OFF_QL);
    uint32_t* Kh  = (uint32_t*)(smraw + OFF_KH);
    uint32_t* Kl  = (uint32_t*)(smraw + OFF_KL);
    uint32_t* Vth = (uint32_t*)(smraw + OFF_VTH);
    uint32_t* Vtl = (uint32_t*)(smraw + OFF_VTL);
    float*    Sf  = (float*)(smraw + OFF_SF);
    uint32_t* Ph  = (uint32_t*)(smraw + OFF_PH);
    uint32_t* Pl  = (uint32_t*)(smraw + OFF_PL);
    float*    rowM = (float*)(smraw + OFF_ST);
    float*    rowL = rowM + 128;
    float*    rowA = rowL + 128;

    const int t = threadIdx.x;
    const int w = t >> 5, lane = t & 31;
    const int g = lane >> 2, cc = lane & 3;
    const int h = blockIdx.x;
    const int qt = 15 - (int)blockIdx.y;
    const int qbase = qt * 128;
    const int qcol = h * HD, kcol = HID + h * HD, vcol = 2 * HID + h * HD;

    {
        const int row = t >> 1;
        const int c0 = (t & 1) * 64;
        const float* src = proj + (size_t)(qbase + row) * P3 + qcol + c0;
        uint32_t* qh = Qh + row * 68 + (c0 >> 1);
        uint32_t* ql = Ql + row * 68 + (c0 >> 1);
#pragma unroll
        for (int i = 0; i < 16; i++) {
            float4 v = *(const float4*)(src + i * 4);
            uint32_t hp, lp;
            split_pair(v.x * NORM, v.y * NORM, hp, lp);
            qh[2 * i] = hp; ql[2 * i] = lp;
            split_pair(v.z * NORM, v.w * NORM, hp, lp);
            qh[2 * i + 1] = hp; ql[2 * i + 1] = lp;
        }
    }
    if (t < 128) { rowM[t] = -3.0e38f; rowL[t] = 0.f; }

    float oacc[16][4];
#pragma unroll
    for (int nt = 0; nt < 16; nt++)
#pragma unroll
        for (int q = 0; q < 4; q++) oacc[nt][q] = 0.f;

    const int nkt = 2 * qt + 2;
    for (int j = 0; j < nkt; j++) {
        __syncthreads();
        {
            const int r = t >> 2;
            const int c0 = (t & 3) * 32;
            const float* src = proj + (size_t)(j * 64 + r) * P3 + kcol + c0;
            uint32_t* kh = Kh + r * 68 + (c0 >> 1);
            uint32_t* kl = Kl + r * 68 + (c0 >> 1);
#pragma unroll
            for (int i = 0; i < 8; i++) {
                float4 v = *(const float4*)(src + i * 4);
                uint32_t hp, lp;
                split_pair(v.x, v.y, hp, lp);
                kh[2 * i] = hp; kl[2 * i] = lp;
                split_pair(v.z, v.w, hp, lp);
                kh[2 * i + 1] = hp; kl[2 * i + 1] = lp;
            }
        }
        {
            const int c = (t & 31) + ((t >> 5) & 3) * 32;
            const int rp0 = (t >> 7) * 16;
            const float* vsrc = proj + (size_t)(j * 64) * P3 + vcol + c;
#pragma unroll
            for (int it = 0; it < 16; it++) {
                const int rp = rp0 + it;
                const float v0 = vsrc[(size_t)(2 * rp) * P3];
                const float v1 = vsrc[(size_t)(2 * rp + 1) * P3];
                uint32_t hp, lp;
                split_pair(v0, v1, hp, lp);
                Vth[c * 36 + rp] = hp;
                Vtl[c * 36 + rp] = lp;
            }
        }
        __syncthreads();

        float sacc[8][4];
#pragma unroll
        for (int nt = 0; nt < 8; nt++)
#pragma unroll
            for (int q = 0; q < 4; q++) sacc[nt][q] = 0.f;

        const uint32_t* q0 = Qh + (w * 16 + g) * 68;
        const uint32_t* q1 = q0 + 8 * 68;
        const uint32_t* q0l = Ql + (w * 16 + g) * 68;
        const uint32_t* q1l = q0l + 8 * 68;
#pragma unroll
        for (int kc = 0; kc < 8; kc++) {
            const int kw = kc * 8;
            uint32_t ah0 = q0[kw + cc], ah1 = q1[kw + cc];
            uint32_t ah2 = q0[kw + cc + 4], ah3 = q1[kw + cc + 4];
            uint32_t al0 = q0l[kw + cc], al1 = q1l[kw + cc];
            uint32_t al2 = q0l[kw + cc + 4], al3 = q1l[kw + cc + 4];
#pragma unroll
            for (int nt = 0; nt < 8; nt++) {
                const int nw = (nt * 8 + g) * 68 + kw;
                uint32_t bh0 = Kh[nw + cc], bh1 = Kh[nw + cc + 4];
                uint32_t bl0 = Kl[nw + cc], bl1 = Kl[nw + cc + 4];
                mma_bf16(sacc[nt][0], sacc[nt][1], sacc[nt][2], sacc[nt][3],
                         ah0, ah1, ah2, ah3, bh0, bh1);
                mma_bf16(sacc[nt][0], sacc[nt][1], sacc[nt][2], sacc[nt][3],
                         ah0, ah1, ah2, ah3, bl0, bl1);
                mma_bf16(sacc[nt][0], sacc[nt][1], sacc[nt][2], sacc[nt][3],
                         al0, al1, al2, al3, bh0, bh1);
            }
        }
        {
            const bool diagt = (j * 64 + 63 > qbase);
            const int r0g = qbase + w * 16 + g;
            float* s0 = Sf + (w * 16 + g) * SSTR;
            float* s1 = s0 + 8 * SSTR;
#pragma unroll
            for (int nt = 0; nt < 8; nt++) {
                const int cg = j * 64 + nt * 8 + 2 * cc;
                float v0 = sacc[nt][0], v1 = sacc[nt][1];
                float v2 = sacc[nt][2], v3 = sacc[nt][3];
                if (diagt) {
                    if (cg     > r0g)     v0 = -1.0e9f;
                    if (cg + 1 > r0g)     v1 = -1.0e9f;
                    if (cg     > r0g + 8) v2 = -1.0e9f;
                    if (cg + 1 > r0g + 8) v3 = -1.0e9f;
                }
                s0[nt * 8 + 2 * cc] = v0; s0[nt * 8 + 2 * cc + 1] = v1;
                s1[nt * 8 + 2 * cc] = v2; s1[nt * 8 + 2 * cc + 1] = v3;
            }
        }
        __syncthreads();

        {
            const int row = t >> 1, half = t & 1;
            const float* pr = Sf + row * SSTR + half * 32;
            float m = -3.0e38f;
#pragma unroll 8
            for (int i = 0; i < 32; i++) m = fmaxf(m, pr[i]);
            m = fmaxf(m, __shfl_xor_sync(0xFFFFFFFFu, m, 1));
            const float mold = rowM[row];
            const float mnew = fmaxf(mold, m);
            float ssum = 0.f;
            uint32_t* ph = Ph + row * 36 + half * 16;
            uint32_t* pl = Pl + row * 36 + half * 16;
#pragma unroll 4
            for (int i = 0; i < 16; i++) {
                const float p0 = __expf(pr[2 * i] - mnew);
                const float p1 = __expf(pr[2 * i + 1] - mnew);
                ssum += p0 + p1;
                uint32_t hp, lp;
                split_pair(p0, p1, hp, lp);
                ph[i] = hp; pl[i] = lp;
            }
            ssum += __shfl_xor_sync(0xFFFFFFFFu, ssum, 1);
            if (half == 0) {
                const float alpha = __expf(mold - mnew);
                rowA[row] = alpha;
                rowL[row] = rowL[row] * alpha + ssum;
                rowM[row] = mnew;
            }
        }
        __syncthreads();

        {
            const float al0 = rowA[w * 16 + g], al1 = rowA[w * 16 + 8 + g];
#pragma unroll
            for (int nt = 0; nt < 16; nt++) {
                oacc[nt][0] *= al0; oacc[nt][1] *= al0;
                oacc[nt][2] *= al1; oacc[nt][3] *= al1;
            }
            const uint32_t* p0 = Ph + (w * 16 + g) * 36;
            const uint32_t* p1 = p0 + 8 * 36;
            const uint32_t* p0l = Pl + (w * 16 + g) * 36;
            const uint32_t* p1l = p0l + 8 * 36;
#pragma unroll
            for (int kc = 0; kc < 4; kc++) {
                const int kw = kc * 8;
                uint32_t ah0 = p0[kw + cc], ah1 = p1[kw + cc];
                uint32_t ah2 = p0[kw + cc + 4], ah3 = p1[kw + cc + 4];
                uint32_t al0f = p0l[kw + cc], al1f = p1l[kw + cc];
                uint32_t al2f = p0l[kw + cc + 4], al3f = p1l[kw + cc + 4];
#pragma unroll
                for (int nt = 0; nt < 16; nt++) {
                    const int nw = (nt * 8 + g) * 36 + kw;
                    uint32_t bh0 = Vth[nw + cc], bh1 = Vth[nw + cc + 4];
                    uint32_t bl0 = Vtl[nw + cc], bl1 = Vtl[nw + cc + 4];
                    mma_bf16(oacc[nt][0], oacc[nt][1], oacc[nt][2], oacc[nt][3],
                             ah0, ah1, ah2, ah3, bh0, bh1);
                    mma_bf16(oacc[nt][0], oacc[nt][1], oacc[nt][2], oacc[nt][3],
                             ah0, ah1, ah2, ah3, bl0, bl1);
                    mma_bf16(oacc[nt][0], oacc[nt][1], oacc[nt][2], oacc[nt][3],
                             al0f, al1f, al2f, al3f, bh0, bh1);
                }
            }
        }
    }

    {
        const float il0 = 1.0f / rowL[w * 16 + g];
        const float il1 = 1.0f / rowL[w * 16 + 8 + g];
        const size_t base0 = (size_t)(qbase + w * 16 + g) * HID + h * HD + 2 * cc;
#pragma unroll
        for (int nt = 0; nt < 16; nt++) {
            *(float2*)(attn_out + base0 + nt * 8) =
                make_float2(oacc[nt][0] * il0, oacc[nt][1] * il0);
            *(float2*)(attn_out + base0 + 8 * HID + nt * 8) =
                make_float2(oacc[nt][2] * il1, oacc[nt][3] * il1);
        }
    }
}

// ---------------- launch ----------------
extern "C" void kernel_launch(void* const* d_in, const int* in_sizes, int n_in,
                              void* d_out, int out_size) {
    (void)in_sizes; (void)n_in; (void)out_size;
    const float* hidden  = (const float*)d_in[0];
    // d_in[1] = attention_mask: deterministic causal -> applied analytically
    const int*   pos_ids = (const int*)d_in[2];
    const float* W_pack  = (const float*)d_in[3];
    const float* W_o     = (const float*)d_in[4];
    float* out = (float*)d_out;

    float *proj = nullptr, *attn = nullptr;
    cudaGetSymbolAddress((void**)&proj, g_proj);
    cudaGetSymbolAddress((void**)&attn, g_attn);
    cudaFuncSetAttribute(attn_bf16, cudaFuncAttributeMaxDynamicSharedMemorySize, ATTN2_SMEM);

    // 1) QKV projection: [2048,4096] @ [12288,4096]^T  (fp16 mma, fp32 accum)
    gemm_fp16mma<<<dim3(P3 / 128, S_LEN / 128), 256>>>(hidden, W_pack, proj,
                                                       S_LEN, P3, HID);
    // 2) RoPE in-place on Q,K
    rope2_kernel<<<S_LEN, 256>>>(proj, pos_ids);
    // 3) causal flash attention (bf16-split tensor cores, fp32-accurate)
    attn_bf16<<<dim3(NH, S_LEN / 128), 256, ATTN2_SMEM>>>(proj, attn);
    // 4) output projection: [2048,4096] @ [4096,4096]^T  (fp16 mma, fp32 accum)
    gemm_fp16mma<<<dim3(HID / 128, S_LEN / 128), 256>>>(attn, W_o, out,
                                                        S_LEN, HID, HID);
}

// round 9
// speedup vs baseline: 1.3848x; 1.3345x over previous
#include <cuda_runtime.h>
#include <cuda_fp16.h>
#include <cstdint>
#include <cstddef>

#define S_LEN 2048
#define HID   4096
#define NH    32
#define HD    128
#define P3    12288   // 3*HID
#define NORM  0.08838834764831845f   // 1/sqrt(128)

// ---------------- scratch (no allocations allowed) ----------------
__device__ float  g_proj[S_LEN * P3];    // QKV (fp32), RoPE in-place
__device__ float  g_attn[S_LEN * HID];   // attention output fp32
__device__ __half g_hid_h[S_LEN * HID];  // fp16 copies for GEMM inputs
__device__ __half g_wp_h[P3 * HID];
__device__ __half g_wo_h[HID * HID];
__device__ __half g_attn_h[S_LEN * HID];

// ---------------- helpers ----------------
__device__ __forceinline__ uint32_t smem_u32(const void* p) {
    uint32_t a;
    asm("{ .reg .u64 t; cvta.to.shared.u64 t, %1; cvt.u32.u64 %0, t; }" : "=r"(a) : "l"(p));
    return a;
}
__device__ __forceinline__ void cp16(uint32_t saddr, const void* gptr) {
    asm volatile("cp.async.ca.shared.global [%0], [%1], 16;" :: "r"(saddr), "l"(gptr));
}
#define CP_COMMIT() asm volatile("cp.async.commit_group;" ::: "memory")
#define CP_WAIT(n)  asm volatile("cp.async.wait_group %0;" :: "n"(n) : "memory")

// mma.sync m16n8k16 fp16, fp32 accum
__device__ __forceinline__ void mma_fp16(float& c0, float& c1, float& c2, float& c3,
                                         uint32_t a0, uint32_t a1, uint32_t a2, uint32_t a3,
                                         uint32_t b0, uint32_t b1) {
    asm volatile(
        "mma.sync.aligned.m16n8k16.row.col.f32.f16.f16.f32 "
        "{%0,%1,%2,%3}, {%4,%5,%6,%7}, {%8,%9}, {%0,%1,%2,%3};"
        : "+f"(c0), "+f"(c1), "+f"(c2), "+f"(c3)
        : "r"(a0), "r"(a1), "r"(a2), "r"(a3), "r"(b0), "r"(b1));
}
// mma.sync m16n8k16 bf16 (attention)
__device__ __forceinline__ void mma_bf16(float& c0, float& c1, float& c2, float& c3,
                                         uint32_t a0, uint32_t a1, uint32_t a2, uint32_t a3,
                                         uint32_t b0, uint32_t b1) {
    asm volatile(
        "mma.sync.aligned.m16n8k16.row.col.f32.bf16.bf16.f32 "
        "{%0,%1,%2,%3}, {%4,%5,%6,%7}, {%8,%9}, {%0,%1,%2,%3};"
        : "+f"(c0), "+f"(c1), "+f"(c2), "+f"(c3)
        : "r"(a0), "r"(a1), "r"(a2), "r"(a3), "r"(b0), "r"(b1));
}
// split fp32 -> hi(bf16)+lo(bf16), pack pairs
__device__ __forceinline__ void split_pair(float x0, float x1, uint32_t& hp, uint32_t& lp) {
    uint16_t h0, h1, l0, l1;
    asm("cvt.rn.bf16.f32 %0, %1;" : "=h"(h0) : "f"(x0));
    asm("cvt.rn.bf16.f32 %0, %1;" : "=h"(h1) : "f"(x1));
    float r0 = x0 - __uint_as_float((uint32_t)h0 << 16);
    float r1 = x1 - __uint_as_float((uint32_t)h1 << 16);
    asm("cvt.rn.bf16.f32 %0, %1;" : "=h"(l0) : "f"(r0));
    asm("cvt.rn.bf16.f32 %0, %1;" : "=h"(l1) : "f"(r1));
    asm("mov.b32 %0, {%1, %2};" : "=r"(hp) : "h"(h0), "h"(h1));
    asm("mov.b32 %0, {%1, %2};" : "=r"(lp) : "h"(l0), "h"(l1));
}

// ---------------- fp32 -> fp16 convert (elementwise, 8/thread) ----------------
__global__ __launch_bounds__(256) void f2h_kernel(const float* __restrict__ src,
                                                  __half* __restrict__ dst, int n) {
    int i = (blockIdx.x * blockDim.x + threadIdx.x) * 8;
    if (i >= n) return;
    float4 a = *(const float4*)(src + i);
    float4 b = *(const float4*)(src + i + 4);
    __half2 h0 = __floats2half2_rn(a.x, a.y);
    __half2 h1 = __floats2half2_rn(a.z, a.w);
    __half2 h2 = __floats2half2_rn(b.x, b.y);
    __half2 h3 = __floats2half2_rn(b.z, b.w);
    uint4 v = {*(uint32_t*)&h0, *(uint32_t*)&h1, *(uint32_t*)&h2, *(uint32_t*)&h3};
    *(uint4*)(dst + i) = v;
}

// ---------------- fp16 cp.async GEMM: C[M,N] = A[M,K] * B[N,K]^T ----------------
// Block 128x128x32, 256 threads (8 warps 2x4, warp tile 64x32), 4-stage cp.async ring.
// SMEM rows: 16 b32 + 4 pad (stride 20) -> frag LDS conflict-free; cp.async dst 16B aligned.
#define KW    20
#define NSTG  4
#define STGW  (2 * 128 * KW)                  // words per stage (A then B)
#define GEMM_SMEM (NSTG * STGW * 4)           // 81920 B

__global__ __launch_bounds__(256, 2) void gemm_fp16ca(const __half* __restrict__ A,
                                                      const __half* __restrict__ B,
                                                      float* __restrict__ C,
                                                      int M, int N, int K) {
    extern __shared__ uint32_t sm[];
    const int t = threadIdx.x;
    const int w = t >> 5, lane = t & 31;
    const int wm = w >> 2, wn = w & 3;
    const int g = lane >> 2, cc = lane & 3;
    const int m0 = blockIdx.y * 128, n0 = blockIdx.x * 128;
    const int KT = K >> 5;

    // cp.async slots: 512 16B-chunks per matrix per ktile; thread does 2 A + 2 B
    const int i0 = 2 * t, i1 = 2 * t + 1;
    const int r0 = i0 >> 2, c0 = i0 & 3;       // row, chunk(8 halves)
    const int r1 = i1 >> 2, c1 = i1 & 3;
    const __half* Ag0 = A + (size_t)(m0 + r0) * K + c0 * 8;
    const __half* Ag1 = A + (size_t)(m0 + r1) * K + c1 * 8;
    const __half* Bg0 = B + (size_t)(n0 + r0) * K + c0 * 8;
    const __half* Bg1 = B + (size_t)(n0 + r1) * K + c1 * 8;
    const uint32_t sbase = smem_u32(sm);
    const uint32_t sa0 = sbase + (r0 * KW + c0 * 4) * 4;
    const uint32_t sa1 = sbase + (r1 * KW + c1 * 4) * 4;
    const uint32_t sb0 = sa0 + 128 * KW * 4;
    const uint32_t sb1 = sa1 + 128 * KW * 4;

    // prologue: stages 0..NSTG-2
#pragma unroll
    for (int s = 0; s < NSTG - 1; s++) {
        const uint32_t so = s * STGW * 4;
        const size_t ko = (size_t)s * 32;
        cp16(sa0 + so, Ag0 + ko);
        cp16(sa1 + so, Ag1 + ko);
        cp16(sb0 + so, Bg0 + ko);
        cp16(sb1 + so, Bg1 + ko);
        CP_COMMIT();
    }

    float acc[4][4][4];
#pragma unroll
    for (int mt = 0; mt < 4; mt++)
#pragma unroll
        for (int nt = 0; nt < 4; nt++)
#pragma unroll
            for (int q = 0; q < 4; q++) acc[mt][nt][q] = 0.f;

    for (int kt = 0; kt < KT; kt++) {
        CP_WAIT(2);          // stage kt complete (<=2 newest groups pending)
        __syncthreads();     // all warps done with stage (kt-1) MMA; data visible
        if (kt + NSTG - 1 < KT) {
            const uint32_t so = ((kt + NSTG - 1) % NSTG) * STGW * 4;
            const size_t ko = (size_t)(kt + NSTG - 1) * 32;
            cp16(sa0 + so, Ag0 + ko);
            cp16(sa1 + so, Ag1 + ko);
            cp16(sb0 + so, Bg0 + ko);
            cp16(sb1 + so, Bg1 + ko);
        }
        CP_COMMIT();

        const uint32_t* Ac = sm + (kt % NSTG) * STGW;
        const uint32_t* Bc = Ac + 128 * KW;
#pragma unroll
        for (int hh = 0; hh < 2; hh++) {       // two k16 chunks
            const int kw = hh * 8;
            uint32_t af[4][4];
#pragma unroll
            for (int mt = 0; mt < 4; mt++) {
                const int r = (wm * 64 + mt * 16 + g) * KW + kw;
                af[mt][0] = Ac[r + cc];
                af[mt][1] = Ac[r + 8 * KW + cc];
                af[mt][2] = Ac[r + cc + 4];
                af[mt][3] = Ac[r + 8 * KW + cc + 4];
            }
            uint32_t bf[4][2];
#pragma unroll
            for (int nt = 0; nt < 4; nt++) {
                const int n = (wn * 32 + nt * 8 + g) * KW + kw;
                bf[nt][0] = Bc[n + cc];
                bf[nt][1] = Bc[n + cc + 4];
            }
#pragma unroll
            for (int mt = 0; mt < 4; mt++)
#pragma unroll
                for (int nt = 0; nt < 4; nt++)
                    mma_fp16(acc[mt][nt][0], acc[mt][nt][1], acc[mt][nt][2], acc[mt][nt][3],
                             af[mt][0], af[mt][1], af[mt][2], af[mt][3],
                             bf[nt][0], bf[nt][1]);
        }
    }

#pragma unroll
    for (int mt = 0; mt < 4; mt++) {
        const int r = m0 + wm * 64 + mt * 16 + g;
#pragma unroll
        for (int nt = 0; nt < 4; nt++) {
            const int n = n0 + wn * 32 + nt * 8 + 2 * cc;
            *(float2*)&C[(size_t)r * N + n]       = make_float2(acc[mt][nt][0], acc[mt][nt][1]);
            *(float2*)&C[(size_t)(r + 8) * N + n] = make_float2(acc[mt][nt][2], acc[mt][nt][3]);
        }
    }
}

// ---------------- RoPE: one block per position, smem trig table ----------------
__global__ __launch_bounds__(256) void rope2_kernel(float* __restrict__ proj,
                                                    const int* __restrict__ pos_ids) {
    __shared__ float ca[64], sa[64];
    const int s = blockIdx.x;
    const int t = threadIdx.x;
    if (t < 64) {
        const int pos = pos_ids[s];
        double inv = exp(-((double)t / 64.0) * 9.210340371976184);
        double a = (double)pos * inv;
        const double twopi = 6.283185307179586476925286766559;
        a -= floor(a / twopi) * twopi;
        sa[t] = sinf((float)a);
        ca[t] = cosf((float)a);
    }
    __syncthreads();
    float* base = proj + (size_t)s * P3;
#pragma unroll
    for (int it = 0; it < 16; it++) {
        const int p = t + it * 256;
        const int d = p & 63;
        const int hh = (p >> 6) & 31;
        float* ptr = base + ((p >> 11) ? HID : 0) + hh * HD + d;
        const float x1 = ptr[0], x2 = ptr[64];
        const float c = ca[d], sn = sa[d];
        ptr[0]  = x1 * c - x2 * sn;
        ptr[64] = x2 * c + x1 * sn;
    }
}

// ---------------- bf16-split tensor-core flash attention (unchanged) ----------------
#define QSTR 136
#define VSTR 72
#define SSTR 65
#define OFF_QH  0
#define OFF_QL  (OFF_QH + 128 * QSTR * 2)
#define OFF_KH  (OFF_QL + 128 * QSTR * 2)
#define OFF_KL  (OFF_KH + 64 * QSTR * 2)
#define OFF_VTH (OFF_KL + 64 * QSTR * 2)
#define OFF_VTL (OFF_VTH + 128 * VSTR * 2)
#define OFF_SF  (OFF_VTL + 128 * VSTR * 2)
#define OFF_PH  (OFF_SF + 128 * SSTR * 4)
#define OFF_PL  (OFF_PH + 128 * VSTR * 2)
#define OFF_ST  (OFF_PL + 128 * VSTR * 2)
#define ATTN2_SMEM (OFF_ST + 3 * 128 * 4)

__global__ __launch_bounds__(256, 1) void attn_bf16(const float* __restrict__ proj,
                                                    float* __restrict__ attn_out) {
    extern __shared__ char smraw[];
    uint32_t* Qh  = (uint32_t*)(smraw + OFF_QH);
    uint32_t* Ql  = (uint32_t*)(smraw + OFF_QL);
    uint32_t* Kh  = (uint32_t*)(smraw + OFF_KH);
    uint32_t* Kl  = (uint32_t*)(smraw + OFF_KL);
    uint32_t* Vth = (uint32_t*)(smraw + OFF_VTH);
    uint32_t* Vtl = (uint32_t*)(smraw + OFF_VTL);
    float*    Sf  = (float*)(smraw + OFF_SF);
    uint32_t* Ph  = (uint32_t*)(smraw + OFF_PH);
    uint32_t* Pl  = (uint32_t*)(smraw + OFF_PL);
    float*    rowM = (float*)(smraw + OFF_ST);
    float*    rowL = rowM + 128;
    float*    rowA = rowL + 128;

    const int t = threadIdx.x;
    const int w = t >> 5, lane = t & 31;
    const int g = lane >> 2, cc = lane & 3;
    const int h = blockIdx.x;
    const int qt = 15 - (int)blockIdx.y;
    const int qbase = qt * 128;
    const int qcol = h * HD, kcol = HID + h * HD, vcol = 2 * HID + h * HD;

    {
        const int row = t >> 1;
        const int c0 = (t & 1) * 64;
        const float* src = proj + (size_t)(qbase + row) * P3 + qcol + c0;
        uint32_t* qh = Qh + row * 68 + (c0 >> 1);
        uint32_t* ql = Ql + row * 68 + (c0 >> 1);
#pragma unroll
        for (int i = 0; i < 16; i++) {
            float4 v = *(const float4*)(src + i * 4);
            uint32_t hp, lp;
            split_pair(v.x * NORM, v.y * NORM, hp, lp);
            qh[2 * i] = hp; ql[2 * i] = lp;
            split_pair(v.z * NORM, v.w * NORM, hp, lp);
            qh[2 * i + 1] = hp; ql[2 * i + 1] = lp;
        }
    }
    if (t < 128) { rowM[t] = -3.0e38f; rowL[t] = 0.f; }

    float oacc[16][4];
#pragma unroll
    for (int nt = 0; nt < 16; nt++)
#pragma unroll
        for (int q = 0; q < 4; q++) oacc[nt][q] = 0.f;

    const int nkt = 2 * qt + 2;
    for (int j = 0; j < nkt; j++) {
        __syncthreads();
        {
            const int r = t >> 2;
            const int c0 = (t & 3) * 32;
            const float* src = proj + (size_t)(j * 64 + r) * P3 + kcol + c0;
            uint32_t* kh = Kh + r * 68 + (c0 >> 1);
            uint32_t* kl = Kl + r * 68 + (c0 >> 1);
#pragma unroll
            for (int i = 0; i < 8; i++) {
                float4 v = *(const float4*)(src + i * 4);
                uint32_t hp, lp;
                split_pair(v.x, v.y, hp, lp);
                kh[2 * i] = hp; kl[2 * i] = lp;
                split_pair(v.z, v.w, hp, lp);
                kh[2 * i + 1] = hp; kl[2 * i + 1] = lp;
            }
        }
        {
            const int c = (t & 31) + ((t >> 5) & 3) * 32;
            const int rp0 = (t >> 7) * 16;
            const float* vsrc = proj + (size_t)(j * 64) * P3 + vcol + c;
#pragma unroll
            for (int it = 0; it < 16; it++) {
                const int rp = rp0 + it;
                const float v0 = vsrc[(size_t)(2 * rp) * P3];
                const float v1 = vsrc[(size_t)(2 * rp + 1) * P3];
                uint32_t hp, lp;
                split_pair(v0, v1, hp, lp);
                Vth[c * 36 + rp] = hp;
                Vtl[c * 36 + rp] = lp;
            }
        }
        __syncthreads();

        float sacc[8][4];
#pragma unroll
        for (int nt = 0; nt < 8; nt++)
#pragma unroll
            for (int q = 0; q < 4; q++) sacc[nt][q] = 0.f;

        const uint32_t* q0 = Qh + (w * 16 + g) * 68;
        const uint32_t* q1 = q0 + 8 * 68;
        const uint32_t* q0l = Ql + (w * 16 + g) * 68;
        const uint32_t* q1l = q0l + 8 * 68;
#pragma unroll
        for (int kc = 0; kc < 8; kc++) {
            const int kw = kc * 8;
            uint32_t ah0 = q0[kw + cc], ah1 = q1[kw + cc];
            uint32_t ah2 = q0[kw + cc + 4], ah3 = q1[kw + cc + 4];
            uint32_t al0 = q0l[kw + cc], al1 = q1l[kw + cc];
            uint32_t al2 = q0l[kw + cc + 4], al3 = q1l[kw + cc + 4];
#pragma unroll
            for (int nt = 0; nt < 8; nt++) {
                const int nw = (nt * 8 + g) * 68 + kw;
                uint32_t bh0 = Kh[nw + cc], bh1 = Kh[nw + cc + 4];
                uint32_t bl0 = Kl[nw + cc], bl1 = Kl[nw + cc + 4];
                mma_bf16(sacc[nt][0], sacc[nt][1], sacc[nt][2], sacc[nt][3],
                         ah0, ah1, ah2, ah3, bh0, bh1);
                mma_bf16(sacc[nt][0], sacc[nt][1], sacc[nt][2], sacc[nt][3],
                         ah0, ah1, ah2, ah3, bl0, bl1);
                mma_bf16(sacc[nt][0], sacc[nt][1], sacc[nt][2], sacc[nt][3],
                         al0, al1, al2, al3, bh0, bh1);
            }
        }
        {
            const bool diagt = (j * 64 + 63 > qbase);
            const int r0g = qbase + w * 16 + g;
            float* s0 = Sf + (w * 16 + g) * SSTR;
            float* s1 = s0 + 8 * SSTR;
#pragma unroll
            for (int nt = 0; nt < 8; nt++) {
                const int cg = j * 64 + nt * 8 + 2 * cc;
                float v0 = sacc[nt][0], v1 = sacc[nt][1];
                float v2 = sacc[nt][2], v3 = sacc[nt][3];
                if (diagt) {
                    if (cg     > r0g)     v0 = -1.0e9f;
                    if (cg + 1 > r0g)     v1 = -1.0e9f;
                    if (cg     > r0g + 8) v2 = -1.0e9f;
                    if (cg + 1 > r0g + 8) v3 = -1.0e9f;
                }
                s0[nt * 8 + 2 * cc] = v0; s0[nt * 8 + 2 * cc + 1] = v1;
                s1[nt * 8 + 2 * cc] = v2; s1[nt * 8 + 2 * cc + 1] = v3;
            }
        }
        __syncthreads();

        {
            const int row = t >> 1, half = t & 1;
            const float* pr = Sf + row * SSTR + half * 32;
            float m = -3.0e38f;
#pragma unroll 8
            for (int i = 0; i < 32; i++) m = fmaxf(m, pr[i]);
            m = fmaxf(m, __shfl_xor_sync(0xFFFFFFFFu, m, 1));
            const float mold = rowM[row];
            const float mnew = fmaxf(mold, m);
            float ssum = 0.f;
            uint32_t* ph = Ph + row * 36 + half * 16;
            uint32_t* pl = Pl + row * 36 + half * 16;
#pragma unroll 4
            for (int i = 0; i < 16; i++) {
                const float p0 = __expf(pr[2 * i] - mnew);
                const float p1 = __expf(pr[2 * i + 1] - mnew);
                ssum += p0 + p1;
                uint32_t hp, lp;
                split_pair(p0, p1, hp, lp);
                ph[i] = hp; pl[i] = lp;
            }
            ssum += __shfl_xor_sync(0xFFFFFFFFu, ssum, 1);
            if (half == 0) {
                const float alpha = __expf(mold - mnew);
                rowA[row] = alpha;
                rowL[row] = rowL[row] * alpha + ssum;
                rowM[row] = mnew;
            }
        }
        __syncthreads();

        {
            const float al0 = rowA[w * 16 + g], al1 = rowA[w * 16 + 8 + g];
#pragma unroll
            for (int nt = 0; nt < 16; nt++) {
                oacc[nt][0] *= al0; oacc[nt][1] *= al0;
                oacc[nt][2] *= al1; oacc[nt][3] *= al1;
            }
            const uint32_t* p0 = Ph + (w * 16 + g) * 36;
            const uint32_t* p1 = p0 + 8 * 36;
            const uint32_t* p0l = Pl + (w * 16 + g) * 36;
            const uint32_t* p1l = p0l + 8 * 36;
#pragma unroll
            for (int kc = 0; kc < 4; kc++) {
                const int kw = kc * 8;
                uint32_t ah0 = p0[kw + cc], ah1 = p1[kw + cc];
                uint32_t ah2 = p0[kw + cc + 4], ah3 = p1[kw + cc + 4];
                uint32_t al0f = p0l[kw + cc], al1f = p1l[kw + cc];
                uint32_t al2f = p0l[kw + cc + 4], al3f = p1l[kw + cc + 4];
#pragma unroll
                for (int nt = 0; nt < 16; nt++) {
                    const int nw = (nt * 8 + g) * 36 + kw;
                    uint32_t bh0 = Vth[nw + cc], bh1 = Vth[nw + cc + 4];
                    uint32_t bl0 = Vtl[nw + cc], bl1 = Vtl[nw + cc + 4];
                    mma_bf16(oacc[nt][0], oacc[nt][1], oacc[nt][2], oacc[nt][3],
                             ah0, ah1, ah2, ah3, bh0, bh1);
                    mma_bf16(oacc[nt][0], oacc[nt][1], oacc[nt][2], oacc[nt][3],
                             ah0, ah1, ah2, ah3, bl0, bl1);
                    mma_bf16(oacc[nt][0], oacc[nt][1], oacc[nt][2], oacc[nt][3],
                             al0f, al1f, al2f, al3f, bh0, bh1);
                }
            }
        }
    }

    {
        const float il0 = 1.0f / rowL[w * 16 + g];
        const float il1 = 1.0f / rowL[w * 16 + 8 + g];
        const size_t base0 = (size_t)(qbase + w * 16 + g) * HID + h * HD + 2 * cc;
#pragma unroll
        for (int nt = 0; nt < 16; nt++) {
            *(float2*)(attn_out + base0 + nt * 8) =
                make_float2(oacc[nt][0] * il0, oacc[nt][1] * il0);
            *(float2*)(attn_out + base0 + 8 * HID + nt * 8) =
                make_float2(oacc[nt][2] * il1, oacc[nt][3] * il1);
        }
    }
}

// ---------------- launch ----------------
extern "C" void kernel_launch(void* const* d_in, const int* in_sizes, int n_in,
                              void* d_out, int out_size) {
    (void)in_sizes; (void)n_in; (void)out_size;
    const float* hidden  = (const float*)d_in[0];
    // d_in[1] = attention_mask: deterministic causal -> applied analytically
    const int*   pos_ids = (const int*)d_in[2];
    const float* W_pack  = (const float*)d_in[3];
    const float* W_o     = (const float*)d_in[4];
    float* out = (float*)d_out;

    float *proj = nullptr, *attn = nullptr;
    __half *hid_h = nullptr, *wp_h = nullptr, *wo_h = nullptr, *attn_h = nullptr;
    cudaGetSymbolAddress((void**)&proj, g_proj);
    cudaGetSymbolAddress((void**)&attn, g_attn);
    cudaGetSymbolAddress((void**)&hid_h, g_hid_h);
    cudaGetSymbolAddress((void**)&wp_h, g_wp_h);
    cudaGetSymbolAddress((void**)&wo_h, g_wo_h);
    cudaGetSymbolAddress((void**)&attn_h, g_attn_h);
    cudaFuncSetAttribute(attn_bf16, cudaFuncAttributeMaxDynamicSharedMemorySize, ATTN2_SMEM);
    cudaFuncSetAttribute(gemm_fp16ca, cudaFuncAttributeMaxDynamicSharedMemorySize, GEMM_SMEM);

    // converts (bandwidth-bound)
    f2h_kernel<<<(S_LEN * HID) / (256 * 8), 256>>>(hidden, hid_h, S_LEN * HID);
    f2h_kernel<<<(P3 * HID) / (256 * 8), 256>>>(W_pack, wp_h, P3 * HID);
    f2h_kernel<<<(HID * HID) / (256 * 8), 256>>>(W_o, wo_h, HID * HID);

    // 1) QKV projection (fp16 cp.async pipeline, fp32 accum)
    gemm_fp16ca<<<dim3(P3 / 128, S_LEN / 128), 256, GEMM_SMEM>>>(hid_h, wp_h, proj,
                                                                 S_LEN, P3, HID);
    // 2) RoPE in-place on Q,K
    rope2_kernel<<<S_LEN, 256>>>(proj, pos_ids);
    // 3) causal flash attention (bf16-split tensor cores)
    attn_bf16<<<dim3(NH, S_LEN / 128), 256, ATTN2_SMEM>>>(proj, attn);
    // 4) output projection
    f2h_kernel<<<(S_LEN * HID) / (256 * 8), 256>>>(attn, attn_h, S_LEN * HID);
    gemm_fp16ca<<<dim3(HID / 128, S_LEN / 128), 256, GEMM_SMEM>>>(attn_h, wo_h, out,
                                                                  S_LEN, HID, HID);
}

// round 10
// speedup vs baseline: 1.4984x; 1.0821x over previous
#include <cuda_runtime.h>
#include <cuda_fp16.h>
#include <cstdint>
#include <cstddef>

#define S_LEN 2048
#define HID   4096
#define NH    32
#define HD    128
#define P3    12288   // 3*HID
#define NORM  0.08838834764831845f   // 1/sqrt(128)

// ---------------- scratch (no allocations allowed) ----------------
__device__ float  g_proj[S_LEN * P3];
__device__ float  g_attn[S_LEN * HID];
__device__ __half g_hid_h[S_LEN * HID];
__device__ __half g_wp_h[P3 * HID];
__device__ __half g_wo_h[HID * HID];
__device__ __half g_attn_h[S_LEN * HID];

// ---------------- helpers ----------------
__device__ __forceinline__ uint32_t smem_u32(const void* p) {
    uint32_t a;
    asm("{ .reg .u64 t; cvta.to.shared.u64 t, %1; cvt.u32.u64 %0, t; }" : "=r"(a) : "l"(p));
    return a;
}
__device__ __forceinline__ void cp16(uint32_t saddr, const void* gptr) {
    asm volatile("cp.async.ca.shared.global [%0], [%1], 16;" :: "r"(saddr), "l"(gptr));
}
#define CP_COMMIT() asm volatile("cp.async.commit_group;" ::: "memory")
#define CP_WAIT(n)  asm volatile("cp.async.wait_group %0;" :: "n"(n) : "memory")

__device__ __forceinline__ void ldsm4(uint32_t& r0, uint32_t& r1, uint32_t& r2, uint32_t& r3,
                                      uint32_t addr) {
    asm volatile("ldmatrix.sync.aligned.m8n8.x4.shared.b16 {%0,%1,%2,%3}, [%4];"
                 : "=r"(r0), "=r"(r1), "=r"(r2), "=r"(r3) : "r"(addr));
}

// mma.sync m16n8k16 fp16, fp32 accum
__device__ __forceinline__ void mma_fp16(float& c0, float& c1, float& c2, float& c3,
                                         uint32_t a0, uint32_t a1, uint32_t a2, uint32_t a3,
                                         uint32_t b0, uint32_t b1) {
    asm volatile(
        "mma.sync.aligned.m16n8k16.row.col.f32.f16.f16.f32 "
        "{%0,%1,%2,%3}, {%4,%5,%6,%7}, {%8,%9}, {%0,%1,%2,%3};"
        : "+f"(c0), "+f"(c1), "+f"(c2), "+f"(c3)
        : "r"(a0), "r"(a1), "r"(a2), "r"(a3), "r"(b0), "r"(b1));
}
// mma.sync m16n8k16 bf16 (attention)
__device__ __forceinline__ void mma_bf16(float& c0, float& c1, float& c2, float& c3,
                                         uint32_t a0, uint32_t a1, uint32_t a2, uint32_t a3,
                                         uint32_t b0, uint32_t b1) {
    asm volatile(
        "mma.sync.aligned.m16n8k16.row.col.f32.bf16.bf16.f32 "
        "{%0,%1,%2,%3}, {%4,%5,%6,%7}, {%8,%9}, {%0,%1,%2,%3};"
        : "+f"(c0), "+f"(c1), "+f"(c2), "+f"(c3)
        : "r"(a0), "r"(a1), "r"(a2), "r"(a3), "r"(b0), "r"(b1));
}
__device__ __forceinline__ void split_pair(float x0, float x1, uint32_t& hp, uint32_t& lp) {
    uint16_t h0, h1, l0, l1;
    asm("cvt.rn.bf16.f32 %0, %1;" : "=h"(h0) : "f"(x0));
    asm("cvt.rn.bf16.f32 %0, %1;" : "=h"(h1) : "f"(x1));
    float r0 = x0 - __uint_as_float((uint32_t)h0 << 16);
    float r1 = x1 - __uint_as_float((uint32_t)h1 << 16);
    asm("cvt.rn.bf16.f32 %0, %1;" : "=h"(l0) : "f"(r0));
    asm("cvt.rn.bf16.f32 %0, %1;" : "=h"(l1) : "f"(r1));
    asm("mov.b32 %0, {%1, %2};" : "=r"(hp) : "h"(h0), "h"(h1));
    asm("mov.b32 %0, {%1, %2};" : "=r"(lp) : "h"(l0), "h"(l1));
}

// ---------------- fp32 -> fp16 convert ----------------
__global__ __launch_bounds__(256) void f2h_kernel(const float* __restrict__ src,
                                                  __half* __restrict__ dst, int n) {
    int i = (blockIdx.x * blockDim.x + threadIdx.x) * 8;
    if (i >= n) return;
    float4 a = *(const float4*)(src + i);
    float4 b = *(const float4*)(src + i + 4);
    __half2 h0 = __floats2half2_rn(a.x, a.y);
    __half2 h1 = __floats2half2_rn(a.z, a.w);
    __half2 h2 = __floats2half2_rn(b.x, b.y);
    __half2 h3 = __floats2half2_rn(b.z, b.w);
    uint4 v = {*(uint32_t*)&h0, *(uint32_t*)&h1, *(uint32_t*)&h2, *(uint32_t*)&h3};
    *(uint4*)(dst + i) = v;
}

// ---------------- fp16 cp.async + ldmatrix GEMM: C = A * B^T ----------------
// Block 128x128x32, 256 threads (8 warps 2x4, warp tile 64x32), 5-stage cp.async ring.
// SMEM row stride 20 words: both ldmatrix phases and cp.async stores conflict-free.
#define KW    20
#define NSTG  5
#define STGW  (2 * 128 * KW)
#define GEMM_SMEM (NSTG * STGW * 4)           // 102400 B

__global__ __launch_bounds__(256, 2) void gemm_fp16ca(const __half* __restrict__ A,
                                                      const __half* __restrict__ B,
                                                      float* __restrict__ C,
                                                      int M, int N, int K) {
    extern __shared__ uint32_t sm[];
    const int t = threadIdx.x;
    const int w = t >> 5, lane = t & 31;
    const int wm = w >> 2, wn = w & 3;
    const int g = lane >> 2, cc = lane & 3;
    const int m0 = blockIdx.y * 128, n0 = blockIdx.x * 128;
    const int KT = K >> 5;
    const uint32_t sbase = smem_u32(sm);

    // cp.async slots: thread covers 2 A + 2 B 16B-chunks per ktile
    const int i0 = 2 * t, i1 = 2 * t + 1;
    const int r0 = i0 >> 2, c0 = i0 & 3;
    const int r1 = i1 >> 2, c1 = i1 & 3;
    const __half* Ag0 = A + (size_t)(m0 + r0) * K + c0 * 8;
    const __half* Ag1 = A + (size_t)(m0 + r1) * K + c1 * 8;
    const __half* Bg0 = B + (size_t)(n0 + r0) * K + c0 * 8;
    const __half* Bg1 = B + (size_t)(n0 + r1) * K + c1 * 8;
    const uint32_t sa0 = sbase + (r0 * KW + c0 * 4) * 4;
    const uint32_t sa1 = sbase + (r1 * KW + c1 * 4) * 4;
    const uint32_t sb0 = sa0 + 128 * KW * 4;
    const uint32_t sb1 = sa1 + 128 * KW * 4;

    // ldmatrix per-lane word offsets (within stage)
    const int lrow = lane & 7, sel = lane >> 3;
    uint32_t a_woff[4], b_woff[2];
#pragma unroll
    for (int mt = 0; mt < 4; mt++)
        a_woff[mt] = (uint32_t)((wm * 64 + mt * 16 + lrow + (sel & 1) * 8) * KW +
                                (sel >> 1) * 4);
#pragma unroll
    for (int p = 0; p < 2; p++)
        b_woff[p] = (uint32_t)(128 * KW +
                               (wn * 32 + p * 16 + (sel >> 1) * 8 + lrow) * KW +
                               (sel & 1) * 4);

    // prologue: stages 0..NSTG-2
#pragma unroll
    for (int s = 0; s < NSTG - 1; s++) {
        const uint32_t so = s * STGW * 4;
        const size_t ko = (size_t)s * 32;
        cp16(sa0 + so, Ag0 + ko);
        cp16(sa1 + so, Ag1 + ko);
        cp16(sb0 + so, Bg0 + ko);
        cp16(sb1 + so, Bg1 + ko);
        CP_COMMIT();
    }

    float acc[4][4][4];
#pragma unroll
    for (int mt = 0; mt < 4; mt++)
#pragma unroll
        for (int nt = 0; nt < 4; nt++)
#pragma unroll
            for (int q = 0; q < 4; q++) acc[mt][nt][q] = 0.f;

    for (int kt = 0; kt < KT; kt++) {
        CP_WAIT(3);
        __syncthreads();
        if (kt + NSTG - 1 < KT) {
            const uint32_t so = ((kt + NSTG - 1) % NSTG) * STGW * 4;
            const size_t ko = (size_t)(kt + NSTG - 1) * 32;
            cp16(sa0 + so, Ag0 + ko);
            cp16(sa1 + so, Ag1 + ko);
            cp16(sb0 + so, Bg0 + ko);
            cp16(sb1 + so, Bg1 + ko);
        }
        CP_COMMIT();

        const uint32_t stgoff = sbase + ((kt % NSTG) * STGW) * 4;
#pragma unroll
        for (int hh = 0; hh < 2; hh++) {
            const uint32_t kwb = stgoff + hh * 8 * 4;
            uint32_t af[4][4], bf[2][4];
#pragma unroll
            for (int mt = 0; mt < 4; mt++)
                ldsm4(af[mt][0], af[mt][1], af[mt][2], af[mt][3], kwb + a_woff[mt] * 4);
#pragma unroll
            for (int p = 0; p < 2; p++)
                ldsm4(bf[p][0], bf[p][1], bf[p][2], bf[p][3], kwb + b_woff[p] * 4);
#pragma unroll
            for (int mt = 0; mt < 4; mt++)
#pragma unroll
                for (int nt = 0; nt < 4; nt++)
                    mma_fp16(acc[mt][nt][0], acc[mt][nt][1], acc[mt][nt][2], acc[mt][nt][3],
                             af[mt][0], af[mt][1], af[mt][2], af[mt][3],
                             bf[nt >> 1][(nt & 1) * 2], bf[nt >> 1][(nt & 1) * 2 + 1]);
        }
    }

#pragma unroll
    for (int mt = 0; mt < 4; mt++) {
        const int r = m0 + wm * 64 + mt * 16 + g;
#pragma unroll
        for (int nt = 0; nt < 4; nt++) {
            const int n = n0 + wn * 32 + nt * 8 + 2 * cc;
            *(float2*)&C[(size_t)r * N + n]       = make_float2(acc[mt][nt][0], acc[mt][nt][1]);
            *(float2*)&C[(size_t)(r + 8) * N + n] = make_float2(acc[mt][nt][2], acc[mt][nt][3]);
        }
    }
}

// ---------------- RoPE ----------------
__global__ __launch_bounds__(256) void rope2_kernel(float* __restrict__ proj,
                                                    const int* __restrict__ pos_ids) {
    __shared__ float ca[64], sa[64];
    const int s = blockIdx.x;
    const int t = threadIdx.x;
    if (t < 64) {
        const int pos = pos_ids[s];
        double inv = exp(-((double)t / 64.0) * 9.210340371976184);
        double a = (double)pos * inv;
        const double twopi = 6.283185307179586476925286766559;
        a -= floor(a / twopi) * twopi;
        sa[t] = sinf((float)a);
        ca[t] = cosf((float)a);
    }
    __syncthreads();
    float* base = proj + (size_t)s * P3;
#pragma unroll
    for (int it = 0; it < 16; it++) {
        const int p = t + it * 256;
        const int d = p & 63;
        const int hh = (p >> 6) & 31;
        float* ptr = base + ((p >> 11) ? HID : 0) + hh * HD + d;
        const float x1 = ptr[0], x2 = ptr[64];
        const float c = ca[d], sn = sa[d];
        ptr[0]  = x1 * c - x2 * sn;
        ptr[64] = x2 * c + x1 * sn;
    }
}

// ---------------- bf16-split tensor-core flash attention (unchanged) ----------------
#define QSTR 136
#define VSTR 72
#define SSTR 65
#define OFF_QH  0
#define OFF_QL  (OFF_QH + 128 * QSTR * 2)
#define OFF_KH  (OFF_QL + 128 * QSTR * 2)
#define OFF_KL  (OFF_KH + 64 * QSTR * 2)
#define OFF_VTH (OFF_KL + 64 * QSTR * 2)
#define OFF_VTL (OFF_VTH + 128 * VSTR * 2)
#define OFF_SF  (OFF_VTL + 128 * VSTR * 2)
#define OFF_PH  (OFF_SF + 128 * SSTR * 4)
#define OFF_PL  (OFF_PH + 128 * VSTR * 2)
#define OFF_ST  (OFF_PL + 128 * VSTR * 2)
#define ATTN2_SMEM (OFF_ST + 3 * 128 * 4)

__global__ __launch_bounds__(256, 1) void attn_bf16(const float* __restrict__ proj,
                                                    float* __restrict__ attn_out) {
    extern __shared__ char smraw[];
    uint32_t* Qh  = (uint32_t*)(smraw + OFF_QH);
    uint32_t* Ql  = (uint32_t*)(smraw + OFF_QL);
    uint32_t* Kh  = (uint32_t*)(smraw + OFF_KH);
    uint32_t* Kl  = (uint32_t*)(smraw + OFF_KL);
    uint32_t* Vth = (uint32_t*)(smraw + OFF_VTH);
    uint32_t* Vtl = (uint32_t*)(smraw + OFF_VTL);
    float*    Sf  = (float*)(smraw + OFF_SF);
    uint32_t* Ph  = (uint32_t*)(smraw + OFF_PH);
    uint32_t* Pl  = (uint32_t*)(smraw + OFF_PL);
    float*    rowM = (float*)(smraw + OFF_ST);
    float*    rowL = rowM + 128;
    float*    rowA = rowL + 128;

    const int t = threadIdx.x;
    const int w = t >> 5, lane = t & 31;
    const int g = lane >> 2, cc = lane & 3;
    const int h = blockIdx.x;
    const int qt = 15 - (int)blockIdx.y;
    const int qbase = qt * 128;
    const int qcol = h * HD, kcol = HID + h * HD, vcol = 2 * HID + h * HD;

    {
        const int row = t >> 1;
        const int c0 = (t & 1) * 64;
        const float* src = proj + (size_t)(qbase + row) * P3 + qcol + c0;
        uint32_t* qh = Qh + row * 68 + (c0 >> 1);
        uint32_t* ql = Ql + row * 68 + (c0 >> 1);
#pragma unroll
        for (int i = 0; i < 16; i++) {
            float4 v = *(const float4*)(src + i * 4);
            uint32_t hp, lp;
            split_pair(v.x * NORM, v.y * NORM, hp, lp);
            qh[2 * i] = hp; ql[2 * i] = lp;
            split_pair(v.z * NORM, v.w * NORM, hp, lp);
            qh[2 * i + 1] = hp; ql[2 * i + 1] = lp;
        }
    }
    if (t < 128) { rowM[t] = -3.0e38f; rowL[t] = 0.f; }

    float oacc[16][4];
#pragma unroll
    for (int nt = 0; nt < 16; nt++)
#pragma unroll
        for (int q = 0; q < 4; q++) oacc[nt][q] = 0.f;

    const int nkt = 2 * qt + 2;
    for (int j = 0; j < nkt; j++) {
        __syncthreads();
        {
            const int r = t >> 2;
            const int c0 = (t & 3) * 32;
            const float* src = proj + (size_t)(j * 64 + r) * P3 + kcol + c0;
            uint32_t* kh = Kh + r * 68 + (c0 >> 1);
            uint32_t* kl = Kl + r * 68 + (c0 >> 1);
#pragma unroll
            for (int i = 0; i < 8; i++) {
                float4 v = *(const float4*)(src + i * 4);
                uint32_t hp, lp;
                split_pair(v.x, v.y, hp, lp);
                kh[2 * i] = hp; kl[2 * i] = lp;
                split_pair(v.z, v.w, hp, lp);
                kh[2 * i + 1] = hp; kl[2 * i + 1] = lp;
            }
        }
        {
            const int c = (t & 31) + ((t >> 5) & 3) * 32;
            const int rp0 = (t >> 7) * 16;
            const float* vsrc = proj + (size_t)(j * 64) * P3 + vcol + c;
#pragma unroll
            for (int it = 0; it < 16; it++) {
                const int rp = rp0 + it;
                const float v0 = vsrc[(size_t)(2 * rp) * P3];
                const float v1 = vsrc[(size_t)(2 * rp + 1) * P3];
                uint32_t hp, lp;
                split_pair(v0, v1, hp, lp);
                Vth[c * 36 + rp] = hp;
                Vtl[c * 36 + rp] = lp;
            }
        }
        __syncthreads();

        float sacc[8][4];
#pragma unroll
        for (int nt = 0; nt < 8; nt++)
#pragma unroll
            for (int q = 0; q < 4; q++) sacc[nt][q] = 0.f;

        const uint32_t* q0 = Qh + (w * 16 + g) * 68;
        const uint32_t* q1 = q0 + 8 * 68;
        const uint32_t* q0l = Ql + (w * 16 + g) * 68;
        const uint32_t* q1l = q0l + 8 * 68;
#pragma unroll
        for (int kc = 0; kc < 8; kc++) {
            const int kw = kc * 8;
            uint32_t ah0 = q0[kw + cc], ah1 = q1[kw + cc];
            uint32_t ah2 = q0[kw + cc + 4], ah3 = q1[kw + cc + 4];
            uint32_t al0 = q0l[kw + cc], al1 = q1l[kw + cc];
            uint32_t al2 = q0l[kw + cc + 4], al3 = q1l[kw + cc + 4];
#pragma unroll
            for (int nt = 0; nt < 8; nt++) {
                const int nw = (nt * 8 + g) * 68 + kw;
                uint32_t bh0 = Kh[nw + cc], bh1 = Kh[nw + cc + 4];
                uint32_t bl0 = Kl[nw + cc], bl1 = Kl[nw + cc + 4];
                mma_bf16(sacc[nt][0], sacc[nt][1], sacc[nt][2], sacc[nt][3],
                         ah0, ah1, ah2, ah3, bh0, bh1);
                mma_bf16(sacc[nt][0], sacc[nt][1], sacc[nt][2], sacc[nt][3],
                         ah0, ah1, ah2, ah3, bl0, bl1);
                mma_bf16(sacc[nt][0], sacc[nt][1], sacc[nt][2], sacc[nt][3],
                         al0, al1, al2, al3, bh0, bh1);
            }
        }
        {
            const bool diagt = (j * 64 + 63 > qbase);
            const int r0g = qbase + w * 16 + g;
            float* s0 = Sf + (w * 16 + g) * SSTR;
            float* s1 = s0 + 8 * SSTR;
#pragma unroll
            for (int nt = 0; nt < 8; nt++) {
                const int cg = j * 64 + nt * 8 + 2 * cc;
                float v0 = sacc[nt][0], v1 = sacc[nt][1];
                float v2 = sacc[nt][2], v3 = sacc[nt][3];
                if (diagt) {
                    if (cg     > r0g)     v0 = -1.0e9f;
                    if (cg + 1 > r0g)     v1 = -1.0e9f;
                    if (cg     > r0g + 8) v2 = -1.0e9f;
                    if (cg + 1 > r0g + 8) v3 = -1.0e9f;
                }
                s0[nt * 8 + 2 * cc] = v0; s0[nt * 8 + 2 * cc + 1] = v1;
                s1[nt * 8 + 2 * cc] = v2; s1[nt * 8 + 2 * cc + 1] = v3;
            }
        }
        __syncthreads();

        {
            const int row = t >> 1, half = t & 1;
            const float* pr = Sf + row * SSTR + half * 32;
            float m = -3.0e38f;
#pragma unroll 8
            for (int i = 0; i < 32; i++) m = fmaxf(m, pr[i]);
            m = fmaxf(m, __shfl_xor_sync(0xFFFFFFFFu, m, 1));
            const float mold = rowM[row];
            const float mnew = fmaxf(mold, m);
            float ssum = 0.f;
            uint32_t* ph = Ph + row * 36 + half * 16;
            uint32_t* pl = Pl + row * 36 + half * 16;
#pragma unroll 4
            for (int i = 0; i < 16; i++) {
                const float p0 = __expf(pr[2 * i] - mnew);
                const float p1 = __expf(pr[2 * i + 1] - mnew);
                ssum += p0 + p1;
                uint32_t hp, lp;
                split_pair(p0, p1, hp, lp);
                ph[i] = hp; pl[i] = lp;
            }
            ssum += __shfl_xor_sync(0xFFFFFFFFu, ssum, 1);
            if (half == 0) {
                const float alpha = __expf(mold - mnew);
                rowA[row] = alpha;
                rowL[row] = rowL[row] * alpha + ssum;
                rowM[row] = mnew;
            }
        }
        __syncthreads();

        {
            const float al0 = rowA[w * 16 + g], al1 = rowA[w * 16 + 8 + g];
#pragma unroll
            for (int nt = 0; nt < 16; nt++) {
                oacc[nt][0] *= al0; oacc[nt][1] *= al0;
                oacc[nt][2] *= al1; oacc[nt][3] *= al1;
            }
            const uint32_t* p0 = Ph + (w * 16 + g) * 36;
            const uint32_t* p1 = p0 + 8 * 36;
            const uint32_t* p0l = Pl + (w * 16 + g) * 36;
            const uint32_t* p1l = p0l + 8 * 36;
#pragma unroll
            for (int kc = 0; kc < 4; kc++) {
                const int kw = kc * 8;
                uint32_t ah0 = p0[kw + cc], ah1 = p1[kw + cc];
                uint32_t ah2 = p0[kw + cc + 4], ah3 = p1[kw + cc + 4];
                uint32_t al0f = p0l[kw + cc], al1f = p1l[kw + cc];
                uint32_t al2f = p0l[kw + cc + 4], al3f = p1l[kw + cc + 4];
#pragma unroll
                for (int nt = 0; nt < 16; nt++) {
                    const int nw = (nt * 8 + g) * 36 + kw;
                    uint32_t bh0 = Vth[nw + cc], bh1 = Vth[nw + cc + 4];
                    uint32_t bl0 = Vtl[nw + cc], bl1 = Vtl[nw + cc + 4];
                    mma_bf16(oacc[nt][0], oacc[nt][1], oacc[nt][2], oacc[nt][3],
                             ah0, ah1, ah2, ah3, bh0, bh1);
                    mma_bf16(oacc[nt][0], oacc[nt][1], oacc[nt][2], oacc[nt][3],
                             ah0, ah1, ah2, ah3, bl0, bl1);
                    mma_bf16(oacc[nt][0], oacc[nt][1], oacc[nt][2], oacc[nt][3],
                             al0f, al1f, al2f, al3f, bh0, bh1);
                }
            }
        }
    }

    {
        const float il0 = 1.0f / rowL[w * 16 + g];
        const float il1 = 1.0f / rowL[w * 16 + 8 + g];
        const size_t base0 = (size_t)(qbase + w * 16 + g) * HID + h * HD + 2 * cc;
#pragma unroll
        for (int nt = 0; nt < 16; nt++) {
            *(float2*)(attn_out + base0 + nt * 8) =
                make_float2(oacc[nt][0] * il0, oacc[nt][1] * il0);
            *(float2*)(attn_out + base0 + 8 * HID + nt * 8) =
                make_float2(oacc[nt][2] * il1, oacc[nt][3] * il1);
        }
    }
}

// ---------------- launch ----------------
extern "C" void kernel_launch(void* const* d_in, const int* in_sizes, int n_in,
                              void* d_out, int out_size) {
    (void)in_sizes; (void)n_in; (void)out_size;
    const float* hidden  = (const float*)d_in[0];
    const int*   pos_ids = (const int*)d_in[2];
    const float* W_pack  = (const float*)d_in[3];
    const float* W_o     = (const float*)d_in[4];
    float* out = (float*)d_out;

    float *proj = nullptr, *attn = nullptr;
    __half *hid_h = nullptr, *wp_h = nullptr, *wo_h = nullptr, *attn_h = nullptr;
    cudaGetSymbolAddress((void**)&proj, g_proj);
    cudaGetSymbolAddress((void**)&attn, g_attn);
    cudaGetSymbolAddress((void**)&hid_h, g_hid_h);
    cudaGetSymbolAddress((void**)&wp_h, g_wp_h);
    cudaGetSymbolAddress((void**)&wo_h, g_wo_h);
    cudaGetSymbolAddress((void**)&attn_h, g_attn_h);
    cudaFuncSetAttribute(attn_bf16, cudaFuncAttributeMaxDynamicSharedMemorySize, ATTN2_SMEM);
    cudaFuncSetAttribute(gemm_fp16ca, cudaFuncAttributeMaxDynamicSharedMemorySize, GEMM_SMEM);

    // converts (bandwidth-bound)
    f2h_kernel<<<(S_LEN * HID) / (256 * 8), 256>>>(hidden, hid_h, S_LEN * HID);
    f2h_kernel<<<(P3 * HID) / (256 * 8), 256>>>(W_pack, wp_h, P3 * HID);
    f2h_kernel<<<(HID * HID) / (256 * 8), 256>>>(W_o, wo_h, HID * HID);

    // 1) QKV projection (fp16 cp.async + ldmatrix, fp32 accum)
    gemm_fp16ca<<<dim3(P3 / 128, S_LEN / 128), 256, GEMM_SMEM>>>(hid_h, wp_h, proj,
                                                                 S_LEN, P3, HID);
    // 2) RoPE in-place on Q,K
    rope2_kernel<<<S_LEN, 256>>>(proj, pos_ids);
    // 3) causal flash attention (bf16-split tensor cores)
    attn_bf16<<<dim3(NH, S_LEN / 128), 256, ATTN2_SMEM>>>(proj, attn);
    // 4) output projection
    f2h_kernel<<<(S_LEN * HID) / (256 * 8), 256>>>(attn, attn_h, S_LEN * HID);
    gemm_fp16ca<<<dim3(HID / 128, S_LEN / 128), 256, GEMM_SMEM>>>(attn_h, wo_h, out,
                                                                  S_LEN, HID, HID);
}

// round 11
// speedup vs baseline: 1.8485x; 1.2336x over previous
#include <cuda_runtime.h>
#include <cuda_fp16.h>
#include <cstdint>
#include <cstddef>

#define S_LEN 2048
#define HID   4096
#define NH    32
#define HD    128
#define P3    12288   // 3*HID
#define NORM  0.08838834764831845f   // 1/sqrt(128)

// ---------------- scratch (no allocations allowed) ----------------
__device__ float  g_proj[S_LEN * P3];
__device__ float  g_attn[S_LEN * HID];
__device__ __half g_hid_h[S_LEN * HID];
__device__ __half g_wp_h[P3 * HID];
__device__ __half g_wo_h[HID * HID];
__device__ __half g_attn_h[S_LEN * HID];

// ---------------- helpers ----------------
__device__ __forceinline__ uint32_t smem_u32(const void* p) {
    uint32_t a;
    asm("{ .reg .u64 t; cvta.to.shared.u64 t, %1; cvt.u32.u64 %0, t; }" : "=r"(a) : "l"(p));
    return a;
}
__device__ __forceinline__ void cp16(uint32_t saddr, const void* gptr) {
    asm volatile("cp.async.ca.shared.global [%0], [%1], 16;" :: "r"(saddr), "l"(gptr));
}
#define CP_COMMIT() asm volatile("cp.async.commit_group;" ::: "memory")
#define CP_WAIT(n)  asm volatile("cp.async.wait_group %0;" :: "n"(n) : "memory")

__device__ __forceinline__ void ldsm4(uint32_t& r0, uint32_t& r1, uint32_t& r2, uint32_t& r3,
                                      uint32_t addr) {
    asm volatile("ldmatrix.sync.aligned.m8n8.x4.shared.b16 {%0,%1,%2,%3}, [%4];"
                 : "=r"(r0), "=r"(r1), "=r"(r2), "=r"(r3) : "r"(addr));
}

// mma.sync m16n8k16 fp16, fp32 accum
__device__ __forceinline__ void mma_fp16(float& c0, float& c1, float& c2, float& c3,
                                         uint32_t a0, uint32_t a1, uint32_t a2, uint32_t a3,
                                         uint32_t b0, uint32_t b1) {
    asm volatile(
        "mma.sync.aligned.m16n8k16.row.col.f32.f16.f16.f32 "
        "{%0,%1,%2,%3}, {%4,%5,%6,%7}, {%8,%9}, {%0,%1,%2,%3};"
        : "+f"(c0), "+f"(c1), "+f"(c2), "+f"(c3)
        : "r"(a0), "r"(a1), "r"(a2), "r"(a3), "r"(b0), "r"(b1));
}
// mma.sync m16n8k16 bf16 (attention)
__device__ __forceinline__ void mma_bf16(float& c0, float& c1, float& c2, float& c3,
                                         uint32_t a0, uint32_t a1, uint32_t a2, uint32_t a3,
                                         uint32_t b0, uint32_t b1) {
    asm volatile(
        "mma.sync.aligned.m16n8k16.row.col.f32.bf16.bf16.f32 "
        "{%0,%1,%2,%3}, {%4,%5,%6,%7}, {%8,%9}, {%0,%1,%2,%3};"
        : "+f"(c0), "+f"(c1), "+f"(c2), "+f"(c3)
        : "r"(a0), "r"(a1), "r"(a2), "r"(a3), "r"(b0), "r"(b1));
}
__device__ __forceinline__ void split_pair(float x0, float x1, uint32_t& hp, uint32_t& lp) {
    uint16_t h0, h1, l0, l1;
    asm("cvt.rn.bf16.f32 %0, %1;" : "=h"(h0) : "f"(x0));
    asm("cvt.rn.bf16.f32 %0, %1;" : "=h"(h1) : "f"(x1));
    float r0 = x0 - __uint_as_float((uint32_t)h0 << 16);
    float r1 = x1 - __uint_as_float((uint32_t)h1 << 16);
    asm("cvt.rn.bf16.f32 %0, %1;" : "=h"(l0) : "f"(r0));
    asm("cvt.rn.bf16.f32 %0, %1;" : "=h"(l1) : "f"(r1));
    asm("mov.b32 %0, {%1, %2};" : "=r"(hp) : "h"(h0), "h"(h1));
    asm("mov.b32 %0, {%1, %2};" : "=r"(lp) : "h"(l0), "h"(l1));
}

// ---------------- fp32 -> fp16 convert ----------------
__global__ __launch_bounds__(256) void f2h_kernel(const float* __restrict__ src,
                                                  __half* __restrict__ dst, int n) {
    int i = (blockIdx.x * blockDim.x + threadIdx.x) * 8;
    if (i >= n) return;
    float4 a = *(const float4*)(src + i);
    float4 b = *(const float4*)(src + i + 4);
    __half2 h0 = __floats2half2_rn(a.x, a.y);
    __half2 h1 = __floats2half2_rn(a.z, a.w);
    __half2 h2 = __floats2half2_rn(b.x, b.y);
    __half2 h3 = __floats2half2_rn(b.z, b.w);
    uint4 v = {*(uint32_t*)&h0, *(uint32_t*)&h1, *(uint32_t*)&h2, *(uint32_t*)&h3};
    *(uint4*)(dst + i) = v;
}

// ---------------- fp16 cp.async + ldmatrix GEMM: C = A * B^T ----------------
// Block 128x256x32, 256 threads (8 warps 2x4), warp tile 64x64, 4-stage cp.async.
// 0.0625 B smem traffic per MAC (was 0.094) -> tensor pipe becomes the limiter.
#define KW    20
#define NSTG  4
#define AW    (128 * KW)                       // A words per stage
#define STGW  ((128 + 256) * KW)               // 7680 words per stage
#define GEMM_SMEM (NSTG * STGW * 4)            // 122880 B

__global__ __launch_bounds__(256, 1) void gemm_fp16ca(const __half* __restrict__ A,
                                                      const __half* __restrict__ B,
                                                      float* __restrict__ C,
                                                      int M, int N, int K) {
    extern __shared__ uint32_t sm[];
    const int t = threadIdx.x;
    const int w = t >> 5, lane = t & 31;
    const int wm = w >> 2, wn = w & 3;         // 2x4 warp grid, warp tile 64x64
    const int g = lane >> 2, cc = lane & 3;
    const int m0 = blockIdx.y * 128, n0 = blockIdx.x * 256;
    const int KT = K >> 5;
    const uint32_t sbase = smem_u32(sm);

    // cp.async: A 512 chunks (2/thread, same row), B 1024 chunks (4/thread, rows +64j)
    const int ar = t >> 1, ac = (t & 1) * 2;
    const __half* AgA = A + (size_t)(m0 + ar) * K + ac * 8;
    const uint32_t saA = sbase + (ar * KW + ac * 4) * 4;
    const int br = t >> 2, bc = t & 3;
    const __half* BgB = B + (size_t)(n0 + br) * K + bc * 8;
    const uint32_t saB = sbase + AW * 4 + (br * KW + bc * 4) * 4;

    // ldmatrix per-lane word offsets (within stage)
    const int lrow = lane & 7, sel = lane >> 3;
    uint32_t a_woff[4], b_woff[4];
#pragma unroll
    for (int mt = 0; mt < 4; mt++)
        a_woff[mt] = (uint32_t)((wm * 64 + mt * 16 + lrow + (sel & 1) * 8) * KW +
                                (sel >> 1) * 4);
#pragma unroll
    for (int p = 0; p < 4; p++)
        b_woff[p] = (uint32_t)(AW + (wn * 64 + p * 16 + (sel >> 1) * 8 + lrow) * KW +
                               (sel & 1) * 4);

    // prologue: stages 0..NSTG-2
#pragma unroll
    for (int s = 0; s < NSTG - 1; s++) {
        const uint32_t so = s * STGW * 4;
        const size_t ko = (size_t)s * 32;
        cp16(saA + so, AgA + ko);
        cp16(saA + so + 16, AgA + ko + 8);
#pragma unroll
        for (int j = 0; j < 4; j++)
            cp16(saB + so + j * (64 * KW * 4), BgB + (size_t)(64 * j) * K + ko);
        CP_COMMIT();
    }

    float acc[4][8][4];
#pragma unroll
    for (int mt = 0; mt < 4; mt++)
#pragma unroll
        for (int nt = 0; nt < 8; nt++)
#pragma unroll
            for (int q = 0; q < 4; q++) acc[mt][nt][q] = 0.f;

    for (int kt = 0; kt < KT; kt++) {
        CP_WAIT(2);
        __syncthreads();
        if (kt + NSTG - 1 < KT) {
            const uint32_t so = ((kt + NSTG - 1) % NSTG) * STGW * 4;
            const size_t ko = (size_t)(kt + NSTG - 1) * 32;
            cp16(saA + so, AgA + ko);
            cp16(saA + so + 16, AgA + ko + 8);
#pragma unroll
            for (int j = 0; j < 4; j++)
                cp16(saB + so + j * (64 * KW * 4), BgB + (size_t)(64 * j) * K + ko);
        }
        CP_COMMIT();

        const uint32_t stgoff = sbase + ((kt % NSTG) * STGW) * 4;
#pragma unroll
        for (int hh = 0; hh < 2; hh++) {
            const uint32_t kwb = stgoff + hh * 8 * 4;
            uint32_t af[4][4], bf[4][4];
#pragma unroll
            for (int mt = 0; mt < 4; mt++)
                ldsm4(af[mt][0], af[mt][1], af[mt][2], af[mt][3], kwb + a_woff[mt] * 4);
#pragma unroll
            for (int p = 0; p < 4; p++)
                ldsm4(bf[p][0], bf[p][1], bf[p][2], bf[p][3], kwb + b_woff[p] * 4);
#pragma unroll
            for (int mt = 0; mt < 4; mt++)
#pragma unroll
                for (int nt = 0; nt < 8; nt++)
                    mma_fp16(acc[mt][nt][0], acc[mt][nt][1], acc[mt][nt][2], acc[mt][nt][3],
                             af[mt][0], af[mt][1], af[mt][2], af[mt][3],
                             bf[nt >> 1][(nt & 1) * 2], bf[nt >> 1][(nt & 1) * 2 + 1]);
        }
    }

#pragma unroll
    for (int mt = 0; mt < 4; mt++) {
        const int r = m0 + wm * 64 + mt * 16 + g;
#pragma unroll
        for (int nt = 0; nt < 8; nt++) {
            const int n = n0 + wn * 64 + nt * 8 + 2 * cc;
            *(float2*)&C[(size_t)r * N + n]       = make_float2(acc[mt][nt][0], acc[mt][nt][1]);
            *(float2*)&C[(size_t)(r + 8) * N + n] = make_float2(acc[mt][nt][2], acc[mt][nt][3]);
        }
    }
}

// ---------------- RoPE ----------------
__global__ __launch_bounds__(256) void rope2_kernel(float* __restrict__ proj,
                                                    const int* __restrict__ pos_ids) {
    __shared__ float ca[64], sa[64];
    const int s = blockIdx.x;
    const int t = threadIdx.x;
    if (t < 64) {
        const int pos = pos_ids[s];
        double inv = exp(-((double)t / 64.0) * 9.210340371976184);
        double a = (double)pos * inv;
        const double twopi = 6.283185307179586476925286766559;
        a -= floor(a / twopi) * twopi;
        sa[t] = sinf((float)a);
        ca[t] = cosf((float)a);
    }
    __syncthreads();
    float* base = proj + (size_t)s * P3;
#pragma unroll
    for (int it = 0; it < 16; it++) {
        const int p = t + it * 256;
        const int d = p & 63;
        const int hh = (p >> 6) & 31;
        float* ptr = base + ((p >> 11) ? HID : 0) + hh * HD + d;
        const float x1 = ptr[0], x2 = ptr[64];
        const float c = ca[d], sn = sa[d];
        ptr[0]  = x1 * c - x2 * sn;
        ptr[64] = x2 * c + x1 * sn;
    }
}

// ---------------- bf16-split tensor-core flash attention (unchanged) ----------------
#define QSTR 136
#define VSTR 72
#define SSTR 65
#define OFF_QH  0
#define OFF_QL  (OFF_QH + 128 * QSTR * 2)
#define OFF_KH  (OFF_QL + 128 * QSTR * 2)
#define OFF_KL  (OFF_KH + 64 * QSTR * 2)
#define OFF_VTH (OFF_KL + 64 * QSTR * 2)
#define OFF_VTL (OFF_VTH + 128 * VSTR * 2)
#define OFF_SF  (OFF_VTL + 128 * VSTR * 2)
#define OFF_PH  (OFF_SF + 128 * SSTR * 4)
#define OFF_PL  (OFF_PH + 128 * VSTR * 2)
#define OFF_ST  (OFF_PL + 128 * VSTR * 2)
#define ATTN2_SMEM (OFF_ST + 3 * 128 * 4)

__global__ __launch_bounds__(256, 1) void attn_bf16(const float* __restrict__ proj,
                                                    float* __restrict__ attn_out) {
    extern __shared__ char smraw[];
    uint32_t* Qh  = (uint32_t*)(smraw + OFF_QH);
    uint32_t* Ql  = (uint32_t*)(smraw + OFF_QL);
    uint32_t* Kh  = (uint32_t*)(smraw + OFF_KH);
    uint32_t* Kl  = (uint32_t*)(smraw + OFF_KL);
    uint32_t* Vth = (uint32_t*)(smraw + OFF_VTH);
    uint32_t* Vtl = (uint32_t*)(smraw + OFF_VTL);
    float*    Sf  = (float*)(smraw + OFF_SF);
    uint32_t* Ph  = (uint32_t*)(smraw + OFF_PH);
    uint32_t* Pl  = (uint32_t*)(smraw + OFF_PL);
    float*    rowM = (float*)(smraw + OFF_ST);
    float*    rowL = rowM + 128;
    float*    rowA = rowL + 128;

    const int t = threadIdx.x;
    const int w = t >> 5, lane = t & 31;
    const int g = lane >> 2, cc = lane & 3;
    const int h = blockIdx.x;
    const int qt = 15 - (int)blockIdx.y;
    const int qbase = qt * 128;
    const int qcol = h * HD, kcol = HID + h * HD, vcol = 2 * HID + h * HD;

    {
        const int row = t >> 1;
        const int c0 = (t & 1) * 64;
        const float* src = proj + (size_t)(qbase + row) * P3 + qcol + c0;
        uint32_t* qh = Qh + row * 68 + (c0 >> 1);
        uint32_t* ql = Ql + row * 68 + (c0 >> 1);
#pragma unroll
        for (int i = 0; i < 16; i++) {
            float4 v = *(const float4*)(src + i * 4);
            uint32_t hp, lp;
            split_pair(v.x * NORM, v.y * NORM, hp, lp);
            qh[2 * i] = hp; ql[2 * i] = lp;
            split_pair(v.z * NORM, v.w * NORM, hp, lp);
            qh[2 * i + 1] = hp; ql[2 * i + 1] = lp;
        }
    }
    if (t < 128) { rowM[t] = -3.0e38f; rowL[t] = 0.f; }

    float oacc[16][4];
#pragma unroll
    for (int nt = 0; nt < 16; nt++)
#pragma unroll
        for (int q = 0; q < 4; q++) oacc[nt][q] = 0.f;

    const int nkt = 2 * qt + 2;
    for (int j = 0; j < nkt; j++) {
        __syncthreads();
        {
            const int r = t >> 2;
            const int c0 = (t & 3) * 32;
            const float* src = proj + (size_t)(j * 64 + r) * P3 + kcol + c0;
            uint32_t* kh = Kh + r * 68 + (c0 >> 1);
            uint32_t* kl = Kl + r * 68 + (c0 >> 1);
#pragma unroll
            for (int i = 0; i < 8; i++) {
                float4 v = *(const float4*)(src + i * 4);
                uint32_t hp, lp;
                split_pair(v.x, v.y, hp, lp);
                kh[2 * i] = hp; kl[2 * i] = lp;
                split_pair(v.z, v.w, hp, lp);
                kh[2 * i + 1] = hp; kl[2 * i + 1] = lp;
            }
        }
        {
            const int c = (t & 31) + ((t >> 5) & 3) * 32;
            const int rp0 = (t >> 7) * 16;
            const float* vsrc = proj + (size_t)(j * 64) * P3 + vcol + c;
#pragma unroll
            for (int it = 0; it < 16; it++) {
                const int rp = rp0 + it;
                const float v0 = vsrc[(size_t)(2 * rp) * P3];
                const float v1 = vsrc[(size_t)(2 * rp + 1) * P3];
                uint32_t hp, lp;
                split_pair(v0, v1, hp, lp);
                Vth[c * 36 + rp] = hp;
                Vtl[c * 36 + rp] = lp;
            }
        }
        __syncthreads();

        float sacc[8][4];
#pragma unroll
        for (int nt = 0; nt < 8; nt++)
#pragma unroll
            for (int q = 0; q < 4; q++) sacc[nt][q] = 0.f;

        const uint32_t* q0 = Qh + (w * 16 + g) * 68;
        const uint32_t* q1 = q0 + 8 * 68;
        const uint32_t* q0l = Ql + (w * 16 + g) * 68;
        const uint32_t* q1l = q0l + 8 * 68;
#pragma unroll
        for (int kc = 0; kc < 8; kc++) {
            const int kw = kc * 8;
            uint32_t ah0 = q0[kw + cc], ah1 = q1[kw + cc];
            uint32_t ah2 = q0[kw + cc + 4], ah3 = q1[kw + cc + 4];
            uint32_t al0 = q0l[kw + cc], al1 = q1l[kw + cc];
            uint32_t al2 = q0l[kw + cc + 4], al3 = q1l[kw + cc + 4];
#pragma unroll
            for (int nt = 0; nt < 8; nt++) {
                const int nw = (nt * 8 + g) * 68 + kw;
                uint32_t bh0 = Kh[nw + cc], bh1 = Kh[nw + cc + 4];
                uint32_t bl0 = Kl[nw + cc], bl1 = Kl[nw + cc + 4];
                mma_bf16(sacc[nt][0], sacc[nt][1], sacc[nt][2], sacc[nt][3],
                         ah0, ah1, ah2, ah3, bh0, bh1);
                mma_bf16(sacc[nt][0], sacc[nt][1], sacc[nt][2], sacc[nt][3],
                         ah0, ah1, ah2, ah3, bl0, bl1);
                mma_bf16(sacc[nt][0], sacc[nt][1], sacc[nt][2], sacc[nt][3],
                         al0, al1, al2, al3, bh0, bh1);
            }
        }
        {
            const bool diagt = (j * 64 + 63 > qbase);
            const int r0g = qbase + w * 16 + g;
            float* s0 = Sf + (w * 16 + g) * SSTR;
            float* s1 = s0 + 8 * SSTR;
#pragma unroll
            for (int nt = 0; nt < 8; nt++) {
                const int cg = j * 64 + nt * 8 + 2 * cc;
                float v0 = sacc[nt][0], v1 = sacc[nt][1];
                float v2 = sacc[nt][2], v3 = sacc[nt][3];
                if (diagt) {
                    if (cg     > r0g)     v0 = -1.0e9f;
                    if (cg + 1 > r0g)     v1 = -1.0e9f;
                    if (cg     > r0g + 8) v2 = -1.0e9f;
                    if (cg + 1 > r0g + 8) v3 = -1.0e9f;
                }
                s0[nt * 8 + 2 * cc] = v0; s0[nt * 8 + 2 * cc + 1] = v1;
                s1[nt * 8 + 2 * cc] = v2; s1[nt * 8 + 2 * cc + 1] = v3;
            }
        }
        __syncthreads();

        {
            const int row = t >> 1, half = t & 1;
            const float* pr = Sf + row * SSTR + half * 32;
            float m = -3.0e38f;
#pragma unroll 8
            for (int i = 0; i < 32; i++) m = fmaxf(m, pr[i]);
            m = fmaxf(m, __shfl_xor_sync(0xFFFFFFFFu, m, 1));
            const float mold = rowM[row];
            const float mnew = fmaxf(mold, m);
            float ssum = 0.f;
            uint32_t* ph = Ph + row * 36 + half * 16;
            uint32_t* pl = Pl + row * 36 + half * 16;
#pragma unroll 4
            for (int i = 0; i < 16; i++) {
                const float p0 = __expf(pr[2 * i] - mnew);
                const float p1 = __expf(pr[2 * i + 1] - mnew);
                ssum += p0 + p1;
                uint32_t hp, lp;
                split_pair(p0, p1, hp, lp);
                ph[i] = hp; pl[i] = lp;
            }
            ssum += __shfl_xor_sync(0xFFFFFFFFu, ssum, 1);
            if (half == 0) {
                const float alpha = __expf(mold - mnew);
                rowA[row] = alpha;
                rowL[row] = rowL[row] * alpha + ssum;
                rowM[row] = mnew;
            }
        }
        __syncthreads();

        {
            const float al0 = rowA[w * 16 + g], al1 = rowA[w * 16 + 8 + g];
#pragma unroll
            for (int nt = 0; nt < 16; nt++) {
                oacc[nt][0] *= al0; oacc[nt][1] *= al0;
                oacc[nt][2] *= al1; oacc[nt][3] *= al1;
            }
            const uint32_t* p0 = Ph + (w * 16 + g) * 36;
            const uint32_t* p1 = p0 + 8 * 36;
            const uint32_t* p0l = Pl + (w * 16 + g) * 36;
            const uint32_t* p1l = p0l + 8 * 36;
#pragma unroll
            for (int kc = 0; kc < 4; kc++) {
                const int kw = kc * 8;
                uint32_t ah0 = p0[kw + cc], ah1 = p1[kw + cc];
                uint32_t ah2 = p0[kw + cc + 4], ah3 = p1[kw + cc + 4];
                uint32_t al0f = p0l[kw + cc], al1f = p1l[kw + cc];
                uint32_t al2f = p0l[kw + cc + 4], al3f = p1l[kw + cc + 4];
#pragma unroll
                for (int nt = 0; nt < 16; nt++) {
                    const int nw = (nt * 8 + g) * 36 + kw;
                    uint32_t bh0 = Vth[nw + cc], bh1 = Vth[nw + cc + 4];
                    uint32_t bl0 = Vtl[nw + cc], bl1 = Vtl[nw + cc + 4];
                    mma_bf16(oacc[nt][0], oacc[nt][1], oacc[nt][2], oacc[nt][3],
                             ah0, ah1, ah2, ah3, bh0, bh1);
                    mma_bf16(oacc[nt][0], oacc[nt][1], oacc[nt][2], oacc[nt][3],
                             ah0, ah1, ah2, ah3, bl0, bl1);
                    mma_bf16(oacc[nt][0], oacc[nt][1], oacc[nt][2], oacc[nt][3],
                             al0f, al1f, al2f, al3f, bh0, bh1);
                }
            }
        }
    }

    {
        const float il0 = 1.0f / rowL[w * 16 + g];
        const float il1 = 1.0f / rowL[w * 16 + 8 + g];
        const size_t base0 = (size_t)(qbase + w * 16 + g) * HID + h * HD + 2 * cc;
#pragma unroll
        for (int nt = 0; nt < 16; nt++) {
            *(float2*)(attn_out + base0 + nt * 8) =
                make_float2(oacc[nt][0] * il0, oacc[nt][1] * il0);
            *(float2*)(attn_out + base0 + 8 * HID + nt * 8) =
                make_float2(oacc[nt][2] * il1, oacc[nt][3] * il1);
        }
    }
}

// ---------------- launch ----------------
extern "C" void kernel_launch(void* const* d_in, const int* in_sizes, int n_in,
                              void* d_out, int out_size) {
    (void)in_sizes; (void)n_in; (void)out_size;
    const float* hidden  = (const float*)d_in[0];
    const int*   pos_ids = (const int*)d_in[2];
    const float* W_pack  = (const float*)d_in[3];
    const float* W_o     = (const float*)d_in[4];
    float* out = (float*)d_out;

    float *proj = nullptr, *attn = nullptr;
    __half *hid_h = nullptr, *wp_h = nullptr, *wo_h = nullptr, *attn_h = nullptr;
    cudaGetSymbolAddress((void**)&proj, g_proj);
    cudaGetSymbolAddress((void**)&attn, g_attn);
    cudaGetSymbolAddress((void**)&hid_h, g_hid_h);
    cudaGetSymbolAddress((void**)&wp_h, g_wp_h);
    cudaGetSymbolAddress((void**)&wo_h, g_wo_h);
    cudaGetSymbolAddress((void**)&attn_h, g_attn_h);
    cudaFuncSetAttribute(attn_bf16, cudaFuncAttributeMaxDynamicSharedMemorySize, ATTN2_SMEM);
    cudaFuncSetAttribute(gemm_fp16ca, cudaFuncAttributeMaxDynamicSharedMemorySize, GEMM_SMEM);

    // converts (bandwidth-bound)
    f2h_kernel<<<(S_LEN * HID) / (256 * 8), 256>>>(hidden, hid_h, S_LEN * HID);
    f2h_kernel<<<(P3 * HID) / (256 * 8), 256>>>(W_pack, wp_h, P3 * HID);
    f2h_kernel<<<(HID * HID) / (256 * 8), 256>>>(W_o, wo_h, HID * HID);

    // 1) QKV projection (fp16 cp.async + ldmatrix, BN=256 tiles)
    gemm_fp16ca<<<dim3(P3 / 256, S_LEN / 128), 256, GEMM_SMEM>>>(hid_h, wp_h, proj,
                                                                 S_LEN, P3, HID);
    // 2) RoPE in-place on Q,K
    rope2_kernel<<<S_LEN, 256>>>(proj, pos_ids);
    // 3) causal flash attention (bf16-split tensor cores)
    attn_bf16<<<dim3(NH, S_LEN / 128), 256, ATTN2_SMEM>>>(proj, attn);
    // 4) output projection
    f2h_kernel<<<(S_LEN * HID) / (256 * 8), 256>>>(attn, attn_h, S_LEN * HID);
    gemm_fp16ca<<<dim3(HID / 256, S_LEN / 128), 256, GEMM_SMEM>>>(attn_h, wo_h, out,
                                                                  S_LEN, HID, HID);
}